// round 4
// baseline (speedup 1.0000x reference)
#include <cuda_runtime.h>
#include <cuda_bf16.h>
#include <cstddef>

#define N_NODES 512
#define H 8

// ---------------- device scratch ----------------
__device__ __align__(16) float g_qh[N_NODES * H * 60];   // q per head, CG*ATTN_NORM folded
__device__ __align__(16) float g_kh[N_NODES * H * 60];
__device__ __align__(16) float g_A[N_NODES * 9 * 64];    // rec part of W1, per node
__device__ __align__(16) float g_B[N_NODES * 9 * 64];    // snd part of W1, per node
__device__ __align__(16) float g_vmT[480 * N_NODES];     // v transposed: [c][n]
__device__ __align__(16) float g_X[(size_t)N_NODES * N_NODES * 64];   // layer1 partial preact
__device__ __align__(16) float g_P[(size_t)H * N_NODES * N_NODES];    // planes [h][r][s]

#define CG1 0.5773502691896258f
#define CG2 0.4472135954999579f
#define ATTN_NORM 0.1889822365046136f
#define RS128 0.08838834764831845f
#define RS64  0.125f
#define RS32  0.17677669529663687f

__device__ __forceinline__ float ftanh(float x) {
    return 1.0f - __fdividef(2.0f, __expf(2.0f * x) + 1.0f);
}

__device__ __forceinline__ unsigned f2tf32(float x) {
    unsigned u;
    asm("cvt.rna.tf32.f32 %0, %1;" : "=r"(u) : "f"(x));
    return u;
}

__device__ __forceinline__ void mma_tf32(float* c, const unsigned* a, unsigned b0, unsigned b1) {
    asm volatile(
        "mma.sync.aligned.m16n8k8.row.col.f32.tf32.tf32.f32 "
        "{%0,%1,%2,%3}, {%4,%5,%6,%7}, {%8,%9}, {%0,%1,%2,%3};\n"
        : "+f"(c[0]), "+f"(c[1]), "+f"(c[2]), "+f"(c[3])
        : "r"(a[0]), "r"(a[1]), "r"(a[2]), "r"(a[3]), "r"(b0), "r"(b1));
}

// ================= Kernel 1: per-node precompute (unchanged from R3) =================
__global__ void __launch_bounds__(256) k_node(
    const float* __restrict__ node_feat,
    const float* __restrict__ Wq0, const float* __restrict__ Wq1, const float* __restrict__ Wq2,
    const float* __restrict__ Wk0, const float* __restrict__ Wk1, const float* __restrict__ Wk2,
    const float* __restrict__ Wv0, const float* __restrict__ Wv1, const float* __restrict__ Wv2,
    const float* __restrict__ mW1)
{
    __shared__ float snf[4 * 480];
    int tid = threadIdx.x;
    int n0 = blockIdx.x * 4;

    for (int i = tid; i < 480; i += 256) {
        int nn = i / 120, c4 = i % 120;
        float4 v = *(const float4*)&node_feat[(size_t)(n0 + nn) * 480 + c4 * 4];
        snf[nn * 480 + c4 * 4 + 0] = v.x;
        snf[nn * 480 + c4 * 4 + 1] = v.y;
        snf[nn * 480 + c4 * 4 + 2] = v.z;
        snf[nn * 480 + c4 * 4 + 3] = v.w;
    }
    __syncthreads();

    for (int g = tid; g < 648; g += 256) {
        int kind, l, m, o, mul, off, mp = 0, stride;
        const float* Wp;
        if (g < 360) {
            int mat = g / 120, gg = g % 120;
            if (gg < 32)      { l = 0; m = 0;              o = gg * 4; }
            else if (gg < 80) { int t = gg - 32; l = 1; o = (t / 3) * 4; m = t % 3; }
            else              { int t = gg - 80; l = 2; o = (t / 5) * 4; m = t % 5; }
            mul = (l == 0) ? 128 : (l == 1) ? 64 : 32;
            off = (l == 0) ? 0 : (l == 1) ? 128 : 320;
            stride = mul;
            if (mat == 0)      Wp = (l == 0) ? Wq0 : (l == 1) ? Wq1 : Wq2;
            else if (mat == 1) Wp = (l == 0) ? Wk0 : (l == 1) ? Wk1 : Wk2;
            else               Wp = (l == 0) ? Wv0 : (l == 1) ? Wv1 : Wv2;
            kind = mat;
        } else {
            int t = g - 360;
            int ab = t / 144, u = t % 144;
            mp = u / 16; o = (u % 16) * 4;
            l = (mp == 0) ? 0 : (mp < 4) ? 1 : 2;
            m = (mp == 0) ? 0 : (mp < 4) ? (mp - 1) : (mp - 4);
            mul = (l == 0) ? 128 : (l == 1) ? 64 : 32;
            off = (l == 0) ? 0 : (l == 1) ? 128 : 320;
            int row = ((l == 0) ? 32 : (l == 1) ? 160 : 224) + ab * 224;
            Wp = mW1 + (size_t)row * 64;
            stride = 64;
            kind = 3 + ab;
        }
        int d = 2 * l + 1;

        float4 a0 = make_float4(0.f,0.f,0.f,0.f), a1 = a0, a2 = a0, a3 = a0;
#pragma unroll 4
        for (int i = 0; i < mul; i++) {
            float4 wv = __ldg((const float4*)&Wp[(size_t)i * stride + o]);
            int col = off + i * d + m;
            float x0 = snf[col], x1 = snf[480 + col], x2 = snf[960 + col], x3 = snf[1440 + col];
            a0.x += x0 * wv.x; a0.y += x0 * wv.y; a0.z += x0 * wv.z; a0.w += x0 * wv.w;
            a1.x += x1 * wv.x; a1.y += x1 * wv.y; a1.z += x1 * wv.z; a1.w += x1 * wv.w;
            a2.x += x2 * wv.x; a2.y += x2 * wv.y; a2.z += x2 * wv.z; a2.w += x2 * wv.w;
            a3.x += x3 * wv.x; a3.y += x3 * wv.y; a3.z += x3 * wv.z; a3.w += x3 * wv.w;
        }

        float rs = (l == 0) ? RS128 : (l == 1) ? RS64 : RS32;
        float cg = (l == 0) ? 1.f   : (l == 1) ? CG1  : CG2;
        float accs[4][4] = {{a0.x,a0.y,a0.z,a0.w},{a1.x,a1.y,a1.z,a1.w},
                            {a2.x,a2.y,a2.z,a2.w},{a3.x,a3.y,a3.z,a3.w}};
#pragma unroll
        for (int nn = 0; nn < 4; nn++) {
            int n = n0 + nn;
#pragma unroll
            for (int oo = 0; oo < 4; oo++) {
                int o_ = o + oo;
                float a = accs[nn][oo];
                if (kind <= 1) {
                    int am = mul >> 3;
                    int hh = o_ / am, oi = o_ % am;
                    int j = (l == 0) ? oi : (l == 1) ? (16 + oi * 3 + m) : (40 + oi * 5 + m);
                    size_t idx = ((size_t)n * H + hh) * 60 + j;
                    if (kind == 0) g_qh[idx] = a * rs * cg * ATTN_NORM;
                    else           g_kh[idx] = a * rs;
                } else if (kind == 2) {
                    int w = (l == 0) ? o_ : (l == 1) ? (128 + o_ * 3 + m) : (320 + o_ * 5 + m);
                    g_vmT[(size_t)w * N_NODES + n] = a * rs;
                } else {
                    float* dst = (kind == 3) ? g_A : g_B;
                    dst[((size_t)n * 9 + mp) * 64 + o_] = a * cg;
                }
            }
        }
    }
}

// ================= Kernel 2: X = b1 + ea*W1a + sh*B[s]  (s-grouped) =================
__global__ void __launch_bounds__(256) k_X(
    const float* __restrict__ edge_attr, const float* __restrict__ edge_sh,
    const float* __restrict__ mW1, const float* __restrict__ mb1)
{
    __shared__ float sW1a[32 * 64];
    __shared__ float sB8[8 * 9 * 64];
    __shared__ float sb1[64];
    int tid = threadIdx.x;
    int st = blockIdx.x & 63, rt = blockIdx.x >> 6;
    int s0 = st * 8, r0 = rt * 64;

    for (int i = tid; i < 2048; i += 256) sW1a[i] = mW1[i];
    for (int i = tid; i < 4608; i += 256) {
        int ss = i / 576, rem = i % 576;
        sB8[i] = g_B[(size_t)(s0 + ss) * 576 + rem];
    }
    if (tid < 64) sb1[tid] = mb1[tid];
    __syncthreads();

#pragma unroll
    for (int it = 0; it < 2; it++) {
        int e = tid + 256 * it;
        int rr = e >> 3, ss = e & 7;
        size_t edge = (size_t)(r0 + rr) * N_NODES + (s0 + ss);

        float ea[32];
        const float4* eap = (const float4*)(edge_attr + edge * 32);
#pragma unroll
        for (int e4 = 0; e4 < 8; e4++) {
            float4 v = __ldg(eap + e4);
            ea[e4*4] = v.x; ea[e4*4+1] = v.y; ea[e4*4+2] = v.z; ea[e4*4+3] = v.w;
        }
        float sh[9];
        const float* shp = edge_sh + edge * 9;
#pragma unroll
        for (int m = 0; m < 9; m++) sh[m] = __ldg(shp + m);

        float* Xp = g_X + edge * 64;
#pragma unroll
        for (int c4 = 0; c4 < 4; c4++) {
            int c0 = c4 * 16;
            float acc[16];
#pragma unroll
            for (int j = 0; j < 16; j++) acc[j] = sb1[c0 + j];
#pragma unroll
            for (int e2 = 0; e2 < 32; e2++) {
                float c = ea[e2];
#pragma unroll
                for (int j4 = 0; j4 < 4; j4++) {
                    float4 w = *(const float4*)&sW1a[e2 * 64 + c0 + j4 * 4];
                    acc[j4*4]   += c * w.x; acc[j4*4+1] += c * w.y;
                    acc[j4*4+2] += c * w.z; acc[j4*4+3] += c * w.w;
                }
            }
#pragma unroll
            for (int m = 0; m < 9; m++) {
                float c = sh[m];
#pragma unroll
                for (int j4 = 0; j4 < 4; j4++) {
                    float4 w = *(const float4*)&sB8[(ss * 9 + m) * 64 + c0 + j4 * 4];
                    acc[j4*4]   += c * w.x; acc[j4*4+1] += c * w.y;
                    acc[j4*4+2] += c * w.z; acc[j4*4+3] += c * w.w;
                }
            }
#pragma unroll
            for (int j4 = 0; j4 < 4; j4++)
                *(float4*)&Xp[c0 + j4 * 4] =
                    make_float4(acc[j4*4], acc[j4*4+1], acc[j4*4+2], acc[j4*4+3]);
        }
    }
}

// ================= Kernel 3: logits GEMM per head: P[h][r][s] = q.k =================
#define QKS 61
__global__ void __launch_bounds__(256) k_logit()
{
    __shared__ float qs[64 * QKS];
    __shared__ float ks[64 * QKS];
    int tid = threadIdx.x;
    int hh = blockIdx.x >> 6, tile = blockIdx.x & 63;
    int r0 = (tile >> 3) * 64, s0 = (tile & 7) * 64;

    for (int i = tid; i < 960; i += 256) {
        int nl = i / 15, k4 = i % 15;
        float4 vq = *(const float4*)&g_qh[((size_t)(r0 + nl) * H + hh) * 60 + k4 * 4];
        float4 vk = *(const float4*)&g_kh[((size_t)(s0 + nl) * H + hh) * 60 + k4 * 4];
        float* qd = &qs[nl * QKS + k4 * 4];
        float* kd = &ks[nl * QKS + k4 * 4];
        qd[0] = vq.x; qd[1] = vq.y; qd[2] = vq.z; qd[3] = vq.w;
        kd[0] = vk.x; kd[1] = vk.y; kd[2] = vk.z; kd[3] = vk.w;
    }
    __syncthreads();

    int tx = tid & 15, ty = tid >> 4;
    float acc[4][4];
#pragma unroll
    for (int i = 0; i < 4; i++)
#pragma unroll
        for (int j = 0; j < 4; j++) acc[i][j] = 0.f;

    for (int k = 0; k < 60; k++) {
        float a_[4], b_[4];
#pragma unroll
        for (int i = 0; i < 4; i++) a_[i] = qs[(ty * 4 + i) * QKS + k];
#pragma unroll
        for (int j = 0; j < 4; j++) b_[j] = ks[(tx * 4 + j) * QKS + k];
#pragma unroll
        for (int i = 0; i < 4; i++)
#pragma unroll
            for (int j = 0; j < 4; j++) acc[i][j] += a_[i] * b_[j];
    }

    float* base = g_P + (size_t)hh * (N_NODES * N_NODES);
#pragma unroll
    for (int i = 0; i < 4; i++) {
        *(float4*)&base[(size_t)(r0 + ty * 4 + i) * N_NODES + s0 + tx * 4] =
            make_float4(acc[i][0], acc[i][1], acc[i][2], acc[i][3]);
    }
}

// ================= Kernel 4: per-r: h1 = tanh(X + sh*A[r]); tensor GEMM2; MLP out =================
#define S1 68
#define SMEM_MLP ((512*S1 + 64*S1 + 576 + 512 + 64 + 8) * 4)

__global__ void __launch_bounds__(256, 1) k_mlp(
    const float* __restrict__ edge_sh,
    const float* __restrict__ mW2, const float* __restrict__ mb2,
    const float* __restrict__ mW3, const float* __restrict__ mb3)
{
    extern __shared__ float sm[];
    float* sh1 = sm;                    // [512][S1], X -> h1 (tf32 bits)
    float* sW2 = sm + 512 * S1;         // [64][S1], tf32 bits
    float* sA  = sW2 + 64 * S1;         // [9][64]
    float* sW3 = sA + 576;              // [64][8]
    float* sb2 = sW3 + 512;
    float* sb3 = sb2 + 64;

    int tid = threadIdx.x;
    int r = blockIdx.x;

    for (int i = tid; i < 4096; i += 256) {
        int k = i >> 6, n = i & 63;
        sW2[k * S1 + n] = __uint_as_float(f2tf32(mW2[i]));
    }
    for (int i = tid; i < 576; i += 256) sA[i] = g_A[(size_t)r * 576 + i];
    for (int i = tid; i < 512; i += 256) sW3[i] = mW3[i];
    if (tid < 64) sb2[tid] = mb2[tid];
    if (tid < 8)  sb3[tid] = mb3[tid];

    // stage X coalesced into sh1
    for (int i = tid; i < 8192; i += 256) {
        int s = i >> 4, k4 = i & 15;
        float4 v = *(const float4*)&g_X[((size_t)r * N_NODES + s) * 64 + k4 * 4];
        float* d = &sh1[s * S1 + k4 * 4];
        d[0] = v.x; d[1] = v.y; d[2] = v.z; d[3] = v.w;
    }
    __syncthreads();

    // add sh*A[r], tanh, convert to tf32 in place
#pragma unroll
    for (int it = 0; it < 2; it++) {
        int s = tid + 256 * it;
        float sh9[9];
        const float* shp = edge_sh + ((size_t)r * N_NODES + s) * 9;
#pragma unroll
        for (int m = 0; m < 9; m++) sh9[m] = __ldg(shp + m);
        float* row = &sh1[s * S1];
#pragma unroll
        for (int c = 0; c < 64; c += 8) {
            float x[8];
#pragma unroll
            for (int j = 0; j < 8; j++) x[j] = row[c + j];
#pragma unroll
            for (int m = 0; m < 9; m++) {
                float cm = sh9[m];
#pragma unroll
                for (int j = 0; j < 8; j++) x[j] += cm * sA[m * 64 + c + j];
            }
#pragma unroll
            for (int j = 0; j < 8; j++) row[c + j] = __uint_as_float(f2tf32(ftanh(x[j])));
        }
    }
    __syncthreads();

    // GEMM2 (tf32 tensor) + epilogue
    int w = tid >> 5, lane = tid & 31;
    int g = lane >> 2, t = lane & 3;

#pragma unroll
    for (int pr = 0; pr < 2; pr++) {
        int mtA = w * 4 + pr * 2;
        float C[2][8][4];
#pragma unroll
        for (int q = 0; q < 2; q++)
#pragma unroll
            for (int nt = 0; nt < 8; nt++)
#pragma unroll
                for (int cc = 0; cc < 4; cc++) C[q][nt][cc] = 0.f;

#pragma unroll
        for (int ksi = 0; ksi < 8; ksi++) {
            unsigned aA[4], aB[4];
            int col = ksi * 8 + t;
            {
                int rA = (mtA) * 16 + g;
                aA[0] = __float_as_uint(sh1[(rA)     * S1 + col]);
                aA[1] = __float_as_uint(sh1[(rA + 8) * S1 + col]);
                aA[2] = __float_as_uint(sh1[(rA)     * S1 + col + 4]);
                aA[3] = __float_as_uint(sh1[(rA + 8) * S1 + col + 4]);
                int rB = (mtA + 1) * 16 + g;
                aB[0] = __float_as_uint(sh1[(rB)     * S1 + col]);
                aB[1] = __float_as_uint(sh1[(rB + 8) * S1 + col]);
                aB[2] = __float_as_uint(sh1[(rB)     * S1 + col + 4]);
                aB[3] = __float_as_uint(sh1[(rB + 8) * S1 + col + 4]);
            }
#pragma unroll
            for (int nt = 0; nt < 8; nt++) {
                unsigned b0 = __float_as_uint(sW2[(ksi * 8 + t)     * S1 + nt * 8 + g]);
                unsigned b1 = __float_as_uint(sW2[(ksi * 8 + t + 4) * S1 + nt * 8 + g]);
                mma_tf32(C[0][nt], aA, b0, b1);
                mma_tf32(C[1][nt], aB, b0, b1);
            }
        }

#pragma unroll
        for (int q = 0; q < 2; q++) {
            int mt = mtA + q;
            float p0[8], p1[8];
#pragma unroll
            for (int h = 0; h < 8; h++) { p0[h] = 0.f; p1[h] = 0.f; }
#pragma unroll
            for (int nt = 0; nt < 8; nt++) {
                int col0 = nt * 8 + 2 * t, col1 = col0 + 1;
                float h00 = ftanh(C[q][nt][0] + sb2[col0]);
                float h01 = ftanh(C[q][nt][1] + sb2[col1]);
                float h10 = ftanh(C[q][nt][2] + sb2[col0]);
                float h11 = ftanh(C[q][nt][3] + sb2[col1]);
#pragma unroll
                for (int h = 0; h < 8; h++) {
                    p0[h] += h00 * sW3[col0 * 8 + h] + h01 * sW3[col1 * 8 + h];
                    p1[h] += h10 * sW3[col0 * 8 + h] + h11 * sW3[col1 * 8 + h];
                }
            }
#pragma unroll
            for (int h = 0; h < 8; h++) {
                p0[h] += __shfl_xor_sync(0xffffffffu, p0[h], 1);
                p0[h] += __shfl_xor_sync(0xffffffffu, p0[h], 2);
                p1[h] += __shfl_xor_sync(0xffffffffu, p1[h], 1);
                p1[h] += __shfl_xor_sync(0xffffffffu, p1[h], 2);
            }
            int sr0 = mt * 16 + g, sr1 = sr0 + 8;
#pragma unroll
            for (int hh2 = 0; hh2 < 2; hh2++) {
                int h = t * 2 + hh2;
                float* P0 = &g_P[(size_t)h * (N_NODES * N_NODES) + (size_t)r * N_NODES + sr0];
                float* P1 = &g_P[(size_t)h * (N_NODES * N_NODES) + (size_t)r * N_NODES + sr1];
                *P0 += p0[h] + sb3[h];
                *P1 += p1[h] + sb3[h];
            }
        }
    }
}

// ================= Kernel 5: softmax over senders + aggregation + residual =================
#define SW_STRIDE 520
#define SMEM3_BYTES (4 * 8 * SW_STRIDE * 4)

__device__ __forceinline__ int h_of(int c) {
    if (c < 128) return c >> 4;
    if (c < 320) return ((c - 128) / 3) >> 3;
    return ((c - 320) / 5) >> 2;
}

__global__ void __launch_bounds__(256) k_out(
    const float* __restrict__ node_feat, float* __restrict__ out)
{
    extern __shared__ float sw[];  // [4][8][520]
    int tid = threadIdx.x;
    int r0 = blockIdx.x * 4;

    // load P planes: sw[rr][h][s]
    for (int i = tid; i < 4096; i += 256) {
        int rr = i >> 10, rem = i & 1023;
        int hh = rem >> 7, s4 = rem & 127;
        float4 v = *(const float4*)&g_P[(size_t)hh * (N_NODES * N_NODES) +
                                        (size_t)(r0 + rr) * N_NODES + s4 * 4];
        float* dst = &sw[(rr * 8 + hh) * SW_STRIDE + s4 * 4];
        dst[0] = v.x; dst[1] = v.y; dst[2] = v.z; dst[3] = v.w;
    }
    __syncthreads();

    int wid = tid >> 5, lane = tid & 31;
    for (int p = wid; p < 32; p += 8) {
        float* row = &sw[p * SW_STRIDE];
        float mx = -1e30f;
#pragma unroll
        for (int k = 0; k < 16; k++) mx = fmaxf(mx, row[lane + 32 * k]);
#pragma unroll
        for (int off = 16; off; off >>= 1) mx = fmaxf(mx, __shfl_xor_sync(0xffffffffu, mx, off));
        float sum = 0.f;
#pragma unroll
        for (int k = 0; k < 16; k++) sum += __expf(row[lane + 32 * k] - mx);
#pragma unroll
        for (int off = 16; off; off >>= 1) sum += __shfl_xor_sync(0xffffffffu, sum, off);
        float rinv = __fdividef(1.0f, sum);
#pragma unroll
        for (int k = 0; k < 16; k++) {
            int s = lane + 32 * k;
            row[s] = __expf(row[s] - mx) * rinv;
        }
    }
    __syncthreads();

    for (int c = wid; c < 480; c += 8) {
        int hh = h_of(c);
        const float* vrow = &g_vmT[(size_t)c * N_NODES];
        const float* w0 = &sw[(0 * 8 + hh) * SW_STRIDE];
        const float* w1 = &sw[(1 * 8 + hh) * SW_STRIDE];
        const float* w2 = &sw[(2 * 8 + hh) * SW_STRIDE];
        const float* w3 = &sw[(3 * 8 + hh) * SW_STRIDE];
        float a0 = 0.f, a1 = 0.f, a2 = 0.f, a3 = 0.f;
#pragma unroll
        for (int k = 0; k < 16; k++) {
            int s = k * 32 + lane;
            float vv = vrow[s];
            a0 += w0[s] * vv; a1 += w1[s] * vv; a2 += w2[s] * vv; a3 += w3[s] * vv;
        }
#pragma unroll
        for (int off = 16; off; off >>= 1) {
            a0 += __shfl_xor_sync(0xffffffffu, a0, off);
            a1 += __shfl_xor_sync(0xffffffffu, a1, off);
            a2 += __shfl_xor_sync(0xffffffffu, a2, off);
            a3 += __shfl_xor_sync(0xffffffffu, a3, off);
        }
        if (lane == 0) {
            out[(size_t)(r0 + 0) * 480 + c] = node_feat[(size_t)(r0 + 0) * 480 + c] + a0;
            out[(size_t)(r0 + 1) * 480 + c] = node_feat[(size_t)(r0 + 1) * 480 + c] + a1;
            out[(size_t)(r0 + 2) * 480 + c] = node_feat[(size_t)(r0 + 2) * 480 + c] + a2;
            out[(size_t)(r0 + 3) * 480 + c] = node_feat[(size_t)(r0 + 3) * 480 + c] + a3;
        }
    }
}

// ================= launch =================
extern "C" void kernel_launch(void* const* d_in, const int* in_sizes, int n_in,
                              void* d_out, int out_size)
{
    const float* node_feat = (const float*)d_in[0];
    const float* edge_attr = (const float*)d_in[1];
    const float* edge_sh   = (const float*)d_in[2];
    const float* Wq0 = (const float*)d_in[3];
    const float* Wq1 = (const float*)d_in[4];
    const float* Wq2 = (const float*)d_in[5];
    const float* Wk0 = (const float*)d_in[6];
    const float* Wk1 = (const float*)d_in[7];
    const float* Wk2 = (const float*)d_in[8];
    const float* Wv0 = (const float*)d_in[9];
    const float* Wv1 = (const float*)d_in[10];
    const float* Wv2 = (const float*)d_in[11];
    const float* mW1 = (const float*)d_in[12];
    const float* mb1 = (const float*)d_in[13];
    const float* mW2 = (const float*)d_in[14];
    const float* mb2 = (const float*)d_in[15];
    const float* mW3 = (const float*)d_in[16];
    const float* mb3 = (const float*)d_in[17];
    float* out = (float*)d_out;

    cudaFuncSetAttribute(k_mlp, cudaFuncAttributeMaxDynamicSharedMemorySize, SMEM_MLP);
    cudaFuncSetAttribute(k_out, cudaFuncAttributeMaxDynamicSharedMemorySize, SMEM3_BYTES);

    k_node<<<128, 256>>>(node_feat, Wq0, Wq1, Wq2, Wk0, Wk1, Wk2, Wv0, Wv1, Wv2, mW1);
    k_X<<<512, 256>>>(edge_attr, edge_sh, mW1, mb1);
    k_logit<<<512, 256>>>();
    k_mlp<<<512, 256, SMEM_MLP>>>(edge_sh, mW2, mb2, mW3, mb3);
    k_out<<<128, 256, SMEM3_BYTES>>>(node_feat, out);
}

// round 5
// speedup vs baseline: 1.3670x; 1.3670x over previous
#include <cuda_runtime.h>
#include <cuda_bf16.h>
#include <cstddef>

#define N_NODES 512
#define H 8

// ---------------- device scratch ----------------
__device__ __align__(16) float g_qh[N_NODES * H * 60];
__device__ __align__(16) float g_kh[N_NODES * H * 60];
__device__ __align__(16) float g_A[N_NODES * 9 * 64];
__device__ __align__(16) float g_B[N_NODES * 9 * 64];
__device__ __align__(16) float g_vmT[480 * N_NODES];
__device__ __align__(16) float g_X[(size_t)N_NODES * N_NODES * 64];
__device__ __align__(16) float g_P[(size_t)H * N_NODES * N_NODES];  // planes [h][r][s]

#define CG1 0.5773502691896258f
#define CG2 0.4472135954999579f
#define ATTN_NORM 0.1889822365046136f
#define RS128 0.08838834764831845f
#define RS64  0.125f
#define RS32  0.17677669529663687f

__device__ __forceinline__ float ftanh(float x) {
    return 1.0f - __fdividef(2.0f, __expf(2.0f * x) + 1.0f);
}

// ================= Kernel 1: per-node precompute (y-split for occupancy) =================
__global__ void __launch_bounds__(256) k_node(
    const float* __restrict__ node_feat,
    const float* __restrict__ Wq0, const float* __restrict__ Wq1, const float* __restrict__ Wq2,
    const float* __restrict__ Wk0, const float* __restrict__ Wk1, const float* __restrict__ Wk2,
    const float* __restrict__ Wv0, const float* __restrict__ Wv1, const float* __restrict__ Wv2,
    const float* __restrict__ mW1)
{
    __shared__ float snf[4 * 480];
    int tid = threadIdx.x;
    int n0 = blockIdx.x * 4;

    for (int i = tid; i < 480; i += 256) {
        int nn = i / 120, c4 = i % 120;
        float4 v = *(const float4*)&node_feat[(size_t)(n0 + nn) * 480 + c4 * 4];
        snf[nn * 480 + c4 * 4 + 0] = v.x;
        snf[nn * 480 + c4 * 4 + 1] = v.y;
        snf[nn * 480 + c4 * 4 + 2] = v.z;
        snf[nn * 480 + c4 * 4 + 3] = v.w;
    }
    __syncthreads();

    int gend = 324 * (blockIdx.y + 1);
    for (int g = tid + 324 * blockIdx.y; g < gend; g += 256) {
        int kind, l, m, o, mul, off, mp = 0, stride;
        const float* Wp;
        if (g < 360) {
            int mat = g / 120, gg = g % 120;
            if (gg < 32)      { l = 0; m = 0;              o = gg * 4; }
            else if (gg < 80) { int t = gg - 32; l = 1; o = (t / 3) * 4; m = t % 3; }
            else              { int t = gg - 80; l = 2; o = (t / 5) * 4; m = t % 5; }
            mul = (l == 0) ? 128 : (l == 1) ? 64 : 32;
            off = (l == 0) ? 0 : (l == 1) ? 128 : 320;
            stride = mul;
            if (mat == 0)      Wp = (l == 0) ? Wq0 : (l == 1) ? Wq1 : Wq2;
            else if (mat == 1) Wp = (l == 0) ? Wk0 : (l == 1) ? Wk1 : Wk2;
            else               Wp = (l == 0) ? Wv0 : (l == 1) ? Wv1 : Wv2;
            kind = mat;
        } else {
            int t = g - 360;
            int ab = t / 144, u = t % 144;
            mp = u / 16; o = (u % 16) * 4;
            l = (mp == 0) ? 0 : (mp < 4) ? 1 : 2;
            m = (mp == 0) ? 0 : (mp < 4) ? (mp - 1) : (mp - 4);
            mul = (l == 0) ? 128 : (l == 1) ? 64 : 32;
            off = (l == 0) ? 0 : (l == 1) ? 128 : 320;
            int row = ((l == 0) ? 32 : (l == 1) ? 160 : 224) + ab * 224;
            Wp = mW1 + (size_t)row * 64;
            stride = 64;
            kind = 3 + ab;
        }
        int d = 2 * l + 1;

        float4 a0 = make_float4(0.f,0.f,0.f,0.f), a1 = a0, a2 = a0, a3 = a0;
#pragma unroll 4
        for (int i = 0; i < mul; i++) {
            float4 wv = __ldg((const float4*)&Wp[(size_t)i * stride + o]);
            int col = off + i * d + m;
            float x0 = snf[col], x1 = snf[480 + col], x2 = snf[960 + col], x3 = snf[1440 + col];
            a0.x += x0 * wv.x; a0.y += x0 * wv.y; a0.z += x0 * wv.z; a0.w += x0 * wv.w;
            a1.x += x1 * wv.x; a1.y += x1 * wv.y; a1.z += x1 * wv.z; a1.w += x1 * wv.w;
            a2.x += x2 * wv.x; a2.y += x2 * wv.y; a2.z += x2 * wv.z; a2.w += x2 * wv.w;
            a3.x += x3 * wv.x; a3.y += x3 * wv.y; a3.z += x3 * wv.z; a3.w += x3 * wv.w;
        }

        float rs = (l == 0) ? RS128 : (l == 1) ? RS64 : RS32;
        float cg = (l == 0) ? 1.f   : (l == 1) ? CG1  : CG2;
        float accs[4][4] = {{a0.x,a0.y,a0.z,a0.w},{a1.x,a1.y,a1.z,a1.w},
                            {a2.x,a2.y,a2.z,a2.w},{a3.x,a3.y,a3.z,a3.w}};
#pragma unroll
        for (int nn = 0; nn < 4; nn++) {
            int n = n0 + nn;
#pragma unroll
            for (int oo = 0; oo < 4; oo++) {
                int o_ = o + oo;
                float a = accs[nn][oo];
                if (kind <= 1) {
                    int am = mul >> 3;
                    int hh = o_ / am, oi = o_ % am;
                    int j = (l == 0) ? oi : (l == 1) ? (16 + oi * 3 + m) : (40 + oi * 5 + m);
                    size_t idx = ((size_t)n * H + hh) * 60 + j;
                    if (kind == 0) g_qh[idx] = a * rs * cg * ATTN_NORM;
                    else           g_kh[idx] = a * rs;
                } else if (kind == 2) {
                    int w = (l == 0) ? o_ : (l == 1) ? (128 + o_ * 3 + m) : (320 + o_ * 5 + m);
                    g_vmT[(size_t)w * N_NODES + n] = a * rs;
                } else {
                    float* dst = (kind == 3) ? g_A : g_B;
                    dst[((size_t)n * 9 + mp) * 64 + o_] = a * cg;
                }
            }
        }
    }
}

// ================= Kernel 2: X = b1 + ea*W1a + sh*B[s]  (GEMM-tiled) =================
__global__ void __launch_bounds__(256) k_X(
    const float* __restrict__ edge_attr, const float* __restrict__ edge_sh,
    const float* __restrict__ mW1, const float* __restrict__ mb1)
{
    __shared__ float eaT[32][132];
    __shared__ float shT[9][132];
    __shared__ float sB[8][576];
    __shared__ float sW1a[32 * 64];
    __shared__ float sb1[64];

    int tid = threadIdx.x;
    int rt = blockIdx.x >> 6, st = blockIdx.x & 63;
    int r0 = rt * 16, s0 = st * 8;

    // ea: 128 edges x 8 float4, transposed into eaT[k][e], e = ss*16+rr
    for (int i = tid; i < 1024; i += 256) {
        int el = i >> 3, k4 = i & 7;
        int rr = el >> 3, ssl = el & 7;
        float4 v = __ldg((const float4*)&edge_attr[((size_t)(r0 + rr) * 512 + s0 + ssl) * 32 + k4 * 4]);
        int e = ssl * 16 + rr;
        eaT[k4*4+0][e] = v.x; eaT[k4*4+1][e] = v.y;
        eaT[k4*4+2][e] = v.z; eaT[k4*4+3][e] = v.w;
    }
    // sh transposed
    for (int i = tid; i < 1152; i += 256) {
        int rr = i / 72, rem = i % 72;
        int ssl = rem / 9, m = rem % 9;
        float v = __ldg(&edge_sh[((size_t)(r0 + rr) * 512 + s0 + ssl) * 9 + m]);
        shT[m][ssl * 16 + rr] = v;
    }
    for (int i = tid; i < 4608; i += 256) {
        int ssl = i / 576, rem = i % 576;
        sB[ssl][rem] = g_B[(size_t)(s0 + ssl) * 576 + rem];
    }
    for (int i = tid; i < 2048; i += 256) sW1a[i] = mW1[i];
    if (tid < 64) sb1[tid] = mb1[tid];
    __syncthreads();

    int ss = tid >> 5, rg = (tid >> 4) & 1, cg = tid & 15;
    int e0 = ss * 16 + rg * 8, c0 = cg * 4;

    float acc[8][4];
#pragma unroll
    for (int j = 0; j < 8; j++) {
        acc[j][0] = sb1[c0]; acc[j][1] = sb1[c0+1];
        acc[j][2] = sb1[c0+2]; acc[j][3] = sb1[c0+3];
    }
#pragma unroll
    for (int k = 0; k < 32; k++) {
        float4 a0 = *(float4*)&eaT[k][e0];
        float4 a1 = *(float4*)&eaT[k][e0 + 4];
        float4 b  = *(float4*)&sW1a[k * 64 + c0];
        float av[8] = {a0.x,a0.y,a0.z,a0.w,a1.x,a1.y,a1.z,a1.w};
#pragma unroll
        for (int j = 0; j < 8; j++) {
            acc[j][0] += av[j]*b.x; acc[j][1] += av[j]*b.y;
            acc[j][2] += av[j]*b.z; acc[j][3] += av[j]*b.w;
        }
    }
#pragma unroll
    for (int m = 0; m < 9; m++) {
        float4 a0 = *(float4*)&shT[m][e0];
        float4 a1 = *(float4*)&shT[m][e0 + 4];
        float4 b  = *(float4*)&sB[ss][m * 64 + c0];
        float av[8] = {a0.x,a0.y,a0.z,a0.w,a1.x,a1.y,a1.z,a1.w};
#pragma unroll
        for (int j = 0; j < 8; j++) {
            acc[j][0] += av[j]*b.x; acc[j][1] += av[j]*b.y;
            acc[j][2] += av[j]*b.z; acc[j][3] += av[j]*b.w;
        }
    }
#pragma unroll
    for (int j = 0; j < 8; j++) {
        int r = r0 + rg * 8 + j, s = s0 + ss;
        *(float4*)&g_X[((size_t)r * 512 + s) * 64 + c0] =
            make_float4(acc[j][0], acc[j][1], acc[j][2], acc[j][3]);
    }
}

// ================= Kernel 3: logits GEMM per head: P[h][r][s] = q.k =================
#define QKS 61
__global__ void __launch_bounds__(256) k_logit()
{
    __shared__ float qs[64 * QKS];
    __shared__ float ks[64 * QKS];
    int tid = threadIdx.x;
    int hh = blockIdx.x >> 6, tile = blockIdx.x & 63;
    int r0 = (tile >> 3) * 64, s0 = (tile & 7) * 64;

    for (int i = tid; i < 960; i += 256) {
        int nl = i / 15, k4 = i % 15;
        float4 vq = *(const float4*)&g_qh[((size_t)(r0 + nl) * H + hh) * 60 + k4 * 4];
        float4 vk = *(const float4*)&g_kh[((size_t)(s0 + nl) * H + hh) * 60 + k4 * 4];
        float* qd = &qs[nl * QKS + k4 * 4];
        float* kd = &ks[nl * QKS + k4 * 4];
        qd[0] = vq.x; qd[1] = vq.y; qd[2] = vq.z; qd[3] = vq.w;
        kd[0] = vk.x; kd[1] = vk.y; kd[2] = vk.z; kd[3] = vk.w;
    }
    __syncthreads();

    int tx = tid & 15, ty = tid >> 4;
    float acc[4][4];
#pragma unroll
    for (int i = 0; i < 4; i++)
#pragma unroll
        for (int j = 0; j < 4; j++) acc[i][j] = 0.f;

    for (int k = 0; k < 60; k++) {
        float a_[4], b_[4];
#pragma unroll
        for (int i = 0; i < 4; i++) a_[i] = qs[(ty * 4 + i) * QKS + k];
#pragma unroll
        for (int j = 0; j < 4; j++) b_[j] = ks[(tx * 4 + j) * QKS + k];
#pragma unroll
        for (int i = 0; i < 4; i++)
#pragma unroll
            for (int j = 0; j < 4; j++) acc[i][j] += a_[i] * b_[j];
    }

    float* base = g_P + (size_t)hh * (N_NODES * N_NODES);
#pragma unroll
    for (int i = 0; i < 4; i++) {
        *(float4*)&base[(size_t)(r0 + ty * 4 + i) * N_NODES + s0 + tx * 4] =
            make_float4(acc[i][0], acc[i][1], acc[i][2], acc[i][3]);
    }
}

// ================= Kernel 4: h1=tanh(X+sh*A[r]); GEMM2; tanh; W3 -> P (fp32) =================
#define H1S 132
#define SMEM_MLP ((64*H1S + 1152 + 64*64 + 576 + 512 + 64 + 8) * 4)

__global__ void __launch_bounds__(256, 1) k_mlp(
    const float* __restrict__ edge_sh,
    const float* __restrict__ mW2, const float* __restrict__ mb2,
    const float* __restrict__ mW3, const float* __restrict__ mb3)
{
    extern __shared__ float sm[];
    float* h1T = sm;                    // [64][H1S]  h1 then h2, transposed [c][s]
    float* shs = h1T + 64 * H1S;        // [1152] = 128 edges x 9
    float* sW2 = shs + 1152;            // [64][64]
    float* sA  = sW2 + 4096;            // [9][64]
    float* sW3 = sA + 576;              // [64][8]
    float* sb2 = sW3 + 512;             // [64]
    float* sb3 = sb2 + 64;              // [8]

    int tid = threadIdx.x;
    int r = blockIdx.x;

    for (int i = tid; i < 4096; i += 256) sW2[i] = mW2[i];
    for (int i = tid; i < 576; i += 256) sA[i] = g_A[(size_t)r * 576 + i];
    for (int i = tid; i < 512; i += 256) sW3[i] = mW3[i];
    if (tid < 64) sb2[tid] = mb2[tid];
    if (tid < 8)  sb3[tid] = mb3[tid];

    int sg = tid >> 4, cgi = tid & 15;

    for (int t = 0; t < 4; t++) {
        int s0 = t * 128;
        __syncthreads();   // protect h1T/shs reuse from previous tile

        // stage sh for this tile (contiguous 1152 floats)
        const float* shg = edge_sh + ((size_t)r * 512 + s0) * 9;
        for (int i = tid; i < 1152; i += 256) shs[i] = __ldg(shg + i);
        __syncthreads();

        // Phase A: h1 = tanh(X + sh*A), store transposed h1T[c][s]
#pragma unroll
        for (int it = 0; it < 2; it++) {
            int item = tid + 256 * it;
            int cq = item & 3, s_l = item >> 2;
            int c0 = cq * 16;
            float acc[16];
            const float4* Xp = (const float4*)&g_X[((size_t)r * 512 + s0 + s_l) * 64 + c0];
#pragma unroll
            for (int v4 = 0; v4 < 4; v4++) {
                float4 v = Xp[v4];
                acc[v4*4] = v.x; acc[v4*4+1] = v.y; acc[v4*4+2] = v.z; acc[v4*4+3] = v.w;
            }
#pragma unroll
            for (int m = 0; m < 9; m++) {
                float cm = shs[s_l * 9 + m];
#pragma unroll
                for (int jj = 0; jj < 16; jj++)
                    acc[jj] += cm * sA[m * 64 + c0 + jj];
            }
#pragma unroll
            for (int jj = 0; jj < 16; jj++)
                h1T[(c0 + jj) * H1S + s_l] = ftanh(acc[jj]);
        }
        __syncthreads();

        // Phase B: GEMM2: acc2[8 s][4 c] over k=0..63
        float acc2[8][4];
#pragma unroll
        for (int j = 0; j < 8; j++)
#pragma unroll
            for (int cc = 0; cc < 4; cc++) acc2[j][cc] = 0.f;

        int sb = sg * 8, c0 = cgi * 4;
#pragma unroll
        for (int k = 0; k < 64; k++) {
            float4 a0 = *(float4*)&h1T[k * H1S + sb];
            float4 a1 = *(float4*)&h1T[k * H1S + sb + 4];
            float4 b  = *(float4*)&sW2[k * 64 + c0];
            float av[8] = {a0.x,a0.y,a0.z,a0.w,a1.x,a1.y,a1.z,a1.w};
#pragma unroll
            for (int j = 0; j < 8; j++) {
                acc2[j][0] += av[j]*b.x; acc2[j][1] += av[j]*b.y;
                acc2[j][2] += av[j]*b.z; acc2[j][3] += av[j]*b.w;
            }
        }
        __syncthreads();   // everyone done reading h1 before overwriting with h2

        // Phase C: h2 = tanh(acc2 + b2) -> h1T[c][s]
#pragma unroll
        for (int j = 0; j < 8; j++)
#pragma unroll
            for (int cc = 0; cc < 4; cc++)
                h1T[(c0 + cc) * H1S + sb + j] = ftanh(acc2[j][cc] + sb2[c0 + cc]);
        __syncthreads();

        // Phase D: p[s][h] = b3 + sum_c h2[s][c]*W3[c][h]; P += p (RMW, coalesced)
#pragma unroll
        for (int i = 0; i < 4; i++) {
            int item = tid + 256 * i;
            int h = item >> 7, s_l = item & 127;
            float p = sb3[h];
#pragma unroll 8
            for (int c = 0; c < 64; c++)
                p += h1T[c * H1S + s_l] * sW3[c * 8 + h];
            float* Pp = &g_P[(size_t)h * (N_NODES * N_NODES) + (size_t)r * 512 + s0 + s_l];
            *Pp += p;
        }
    }
}

// ================= Kernel 5: softmax + aggregation + residual =================
#define SW_STRIDE 520
#define SMEM3_BYTES (4 * 8 * SW_STRIDE * 4)

__device__ __forceinline__ int h_of(int c) {
    if (c < 128) return c >> 4;
    if (c < 320) return ((c - 128) / 3) >> 3;
    return ((c - 320) / 5) >> 2;
}

__global__ void __launch_bounds__(256) k_out(
    const float* __restrict__ node_feat, float* __restrict__ out)
{
    extern __shared__ float sw[];  // [4][8][520]
    int tid = threadIdx.x;
    int r0 = blockIdx.x * 4;

    for (int i = tid; i < 4096; i += 256) {
        int rr = i >> 10, rem = i & 1023;
        int hh = rem >> 7, s4 = rem & 127;
        float4 v = *(const float4*)&g_P[(size_t)hh * (N_NODES * N_NODES) +
                                        (size_t)(r0 + rr) * N_NODES + s4 * 4];
        float* dst = &sw[(rr * 8 + hh) * SW_STRIDE + s4 * 4];
        dst[0] = v.x; dst[1] = v.y; dst[2] = v.z; dst[3] = v.w;
    }
    __syncthreads();

    int wid = tid >> 5, lane = tid & 31;
    for (int p = wid; p < 32; p += 8) {
        float* row = &sw[p * SW_STRIDE];
        float mx = -1e30f;
#pragma unroll
        for (int k = 0; k < 16; k++) mx = fmaxf(mx, row[lane + 32 * k]);
#pragma unroll
        for (int off = 16; off; off >>= 1) mx = fmaxf(mx, __shfl_xor_sync(0xffffffffu, mx, off));
        float sum = 0.f;
#pragma unroll
        for (int k = 0; k < 16; k++) sum += __expf(row[lane + 32 * k] - mx);
#pragma unroll
        for (int off = 16; off; off >>= 1) sum += __shfl_xor_sync(0xffffffffu, sum, off);
        float rinv = __fdividef(1.0f, sum);
#pragma unroll
        for (int k = 0; k < 16; k++) {
            int s = lane + 32 * k;
            row[s] = __expf(row[s] - mx) * rinv;
        }
    }
    __syncthreads();

    for (int c = wid; c < 480; c += 8) {
        int hh = h_of(c);
        const float* vrow = &g_vmT[(size_t)c * N_NODES];
        const float* w0 = &sw[(0 * 8 + hh) * SW_STRIDE];
        const float* w1 = &sw[(1 * 8 + hh) * SW_STRIDE];
        const float* w2 = &sw[(2 * 8 + hh) * SW_STRIDE];
        const float* w3 = &sw[(3 * 8 + hh) * SW_STRIDE];
        float a0 = 0.f, a1 = 0.f, a2 = 0.f, a3 = 0.f;
#pragma unroll
        for (int k = 0; k < 16; k++) {
            int s = k * 32 + lane;
            float vv = vrow[s];
            a0 += w0[s] * vv; a1 += w1[s] * vv; a2 += w2[s] * vv; a3 += w3[s] * vv;
        }
#pragma unroll
        for (int off = 16; off; off >>= 1) {
            a0 += __shfl_xor_sync(0xffffffffu, a0, off);
            a1 += __shfl_xor_sync(0xffffffffu, a1, off);
            a2 += __shfl_xor_sync(0xffffffffu, a2, off);
            a3 += __shfl_xor_sync(0xffffffffu, a3, off);
        }
        if (lane == 0) {
            out[(size_t)(r0 + 0) * 480 + c] = node_feat[(size_t)(r0 + 0) * 480 + c] + a0;
            out[(size_t)(r0 + 1) * 480 + c] = node_feat[(size_t)(r0 + 1) * 480 + c] + a1;
            out[(size_t)(r0 + 2) * 480 + c] = node_feat[(size_t)(r0 + 2) * 480 + c] + a2;
            out[(size_t)(r0 + 3) * 480 + c] = node_feat[(size_t)(r0 + 3) * 480 + c] + a3;
        }
    }
}

// ================= launch =================
extern "C" void kernel_launch(void* const* d_in, const int* in_sizes, int n_in,
                              void* d_out, int out_size)
{
    const float* node_feat = (const float*)d_in[0];
    const float* edge_attr = (const float*)d_in[1];
    const float* edge_sh   = (const float*)d_in[2];
    const float* Wq0 = (const float*)d_in[3];
    const float* Wq1 = (const float*)d_in[4];
    const float* Wq2 = (const float*)d_in[5];
    const float* Wk0 = (const float*)d_in[6];
    const float* Wk1 = (const float*)d_in[7];
    const float* Wk2 = (const float*)d_in[8];
    const float* Wv0 = (const float*)d_in[9];
    const float* Wv1 = (const float*)d_in[10];
    const float* Wv2 = (const float*)d_in[11];
    const float* mW1 = (const float*)d_in[12];
    const float* mb1 = (const float*)d_in[13];
    const float* mW2 = (const float*)d_in[14];
    const float* mb2 = (const float*)d_in[15];
    const float* mW3 = (const float*)d_in[16];
    const float* mb3 = (const float*)d_in[17];
    float* out = (float*)d_out;

    cudaFuncSetAttribute(k_mlp, cudaFuncAttributeMaxDynamicSharedMemorySize, SMEM_MLP);
    cudaFuncSetAttribute(k_out, cudaFuncAttributeMaxDynamicSharedMemorySize, SMEM3_BYTES);

    k_node<<<dim3(128, 2), 256>>>(node_feat, Wq0, Wq1, Wq2, Wk0, Wk1, Wk2, Wv0, Wv1, Wv2, mW1);
    k_X<<<2048, 256>>>(edge_attr, edge_sh, mW1, mb1);
    k_logit<<<512, 256>>>();
    k_mlp<<<512, 256, SMEM_MLP>>>(edge_sh, mW2, mb2, mW3, mb3);
    k_out<<<128, 256, SMEM3_BYTES>>>(node_feat, out);
}

// round 6
// speedup vs baseline: 1.5087x; 1.1037x over previous
#include <cuda_runtime.h>
#include <cuda_bf16.h>
#include <cstddef>

#define N_NODES 512
#define H 8

// ---------------- device scratch ----------------
__device__ __align__(16) float g_qh[N_NODES * H * 60];
__device__ __align__(16) float g_kh[N_NODES * H * 60];
__device__ __align__(16) float g_A[N_NODES * 9 * 64];
__device__ __align__(16) float g_B[N_NODES * 9 * 64];
__device__ __align__(16) float g_vmT[480 * N_NODES];
__device__ __align__(16) float g_X[(size_t)N_NODES * N_NODES * 64];
__device__ __align__(16) float g_P[(size_t)H * N_NODES * N_NODES];  // planes [h][r][s]

#define CG1 0.5773502691896258f
#define CG2 0.4472135954999579f
#define ATTN_NORM 0.1889822365046136f
#define RS128 0.08838834764831845f
#define RS64  0.125f
#define RS32  0.17677669529663687f

__device__ __forceinline__ float ftanh(float x) {
    return 1.0f - __fdividef(2.0f, __expf(2.0f * x) + 1.0f);
}

// ================= Kernel 1: per-node precompute =================
__global__ void __launch_bounds__(256) k_node(
    const float* __restrict__ node_feat,
    const float* __restrict__ Wq0, const float* __restrict__ Wq1, const float* __restrict__ Wq2,
    const float* __restrict__ Wk0, const float* __restrict__ Wk1, const float* __restrict__ Wk2,
    const float* __restrict__ Wv0, const float* __restrict__ Wv1, const float* __restrict__ Wv2,
    const float* __restrict__ mW1)
{
    __shared__ float snf[4 * 480];
    int tid = threadIdx.x;
    int n0 = blockIdx.x * 4;

    for (int i = tid; i < 480; i += 256) {
        int nn = i / 120, c4 = i % 120;
        float4 v = *(const float4*)&node_feat[(size_t)(n0 + nn) * 480 + c4 * 4];
        snf[nn * 480 + c4 * 4 + 0] = v.x;
        snf[nn * 480 + c4 * 4 + 1] = v.y;
        snf[nn * 480 + c4 * 4 + 2] = v.z;
        snf[nn * 480 + c4 * 4 + 3] = v.w;
    }
    __syncthreads();

    int gend = 324 * (blockIdx.y + 1);
    for (int g = tid + 324 * blockIdx.y; g < gend; g += 256) {
        int kind, l, m, o, mul, off, mp = 0, stride;
        const float* Wp;
        if (g < 360) {
            int mat = g / 120, gg = g % 120;
            if (gg < 32)      { l = 0; m = 0;              o = gg * 4; }
            else if (gg < 80) { int t = gg - 32; l = 1; o = (t / 3) * 4; m = t % 3; }
            else              { int t = gg - 80; l = 2; o = (t / 5) * 4; m = t % 5; }
            mul = (l == 0) ? 128 : (l == 1) ? 64 : 32;
            off = (l == 0) ? 0 : (l == 1) ? 128 : 320;
            stride = mul;
            if (mat == 0)      Wp = (l == 0) ? Wq0 : (l == 1) ? Wq1 : Wq2;
            else if (mat == 1) Wp = (l == 0) ? Wk0 : (l == 1) ? Wk1 : Wk2;
            else               Wp = (l == 0) ? Wv0 : (l == 1) ? Wv1 : Wv2;
            kind = mat;
        } else {
            int t = g - 360;
            int ab = t / 144, u = t % 144;
            mp = u / 16; o = (u % 16) * 4;
            l = (mp == 0) ? 0 : (mp < 4) ? 1 : 2;
            m = (mp == 0) ? 0 : (mp < 4) ? (mp - 1) : (mp - 4);
            mul = (l == 0) ? 128 : (l == 1) ? 64 : 32;
            off = (l == 0) ? 0 : (l == 1) ? 128 : 320;
            int row = ((l == 0) ? 32 : (l == 1) ? 160 : 224) + ab * 224;
            Wp = mW1 + (size_t)row * 64;
            stride = 64;
            kind = 3 + ab;
        }
        int d = 2 * l + 1;

        float4 a0 = make_float4(0.f,0.f,0.f,0.f), a1 = a0, a2 = a0, a3 = a0;
#pragma unroll 4
        for (int i = 0; i < mul; i++) {
            float4 wv = __ldg((const float4*)&Wp[(size_t)i * stride + o]);
            int col = off + i * d + m;
            float x0 = snf[col], x1 = snf[480 + col], x2 = snf[960 + col], x3 = snf[1440 + col];
            a0.x += x0 * wv.x; a0.y += x0 * wv.y; a0.z += x0 * wv.z; a0.w += x0 * wv.w;
            a1.x += x1 * wv.x; a1.y += x1 * wv.y; a1.z += x1 * wv.z; a1.w += x1 * wv.w;
            a2.x += x2 * wv.x; a2.y += x2 * wv.y; a2.z += x2 * wv.z; a2.w += x2 * wv.w;
            a3.x += x3 * wv.x; a3.y += x3 * wv.y; a3.z += x3 * wv.z; a3.w += x3 * wv.w;
        }

        float rs = (l == 0) ? RS128 : (l == 1) ? RS64 : RS32;
        float cg = (l == 0) ? 1.f   : (l == 1) ? CG1  : CG2;
        float accs[4][4] = {{a0.x,a0.y,a0.z,a0.w},{a1.x,a1.y,a1.z,a1.w},
                            {a2.x,a2.y,a2.z,a2.w},{a3.x,a3.y,a3.z,a3.w}};
#pragma unroll
        for (int nn = 0; nn < 4; nn++) {
            int n = n0 + nn;
#pragma unroll
            for (int oo = 0; oo < 4; oo++) {
                int o_ = o + oo;
                float a = accs[nn][oo];
                if (kind <= 1) {
                    int am = mul >> 3;
                    int hh = o_ / am, oi = o_ % am;
                    int j = (l == 0) ? oi : (l == 1) ? (16 + oi * 3 + m) : (40 + oi * 5 + m);
                    size_t idx = ((size_t)n * H + hh) * 60 + j;
                    if (kind == 0) g_qh[idx] = a * rs * cg * ATTN_NORM;
                    else           g_kh[idx] = a * rs;
                } else if (kind == 2) {
                    int w = (l == 0) ? o_ : (l == 1) ? (128 + o_ * 3 + m) : (320 + o_ * 5 + m);
                    g_vmT[(size_t)w * N_NODES + n] = a * rs;
                } else {
                    float* dst = (kind == 3) ? g_A : g_B;
                    dst[((size_t)n * 9 + mp) * 64 + o_] = a * cg;
                }
            }
        }
    }
}

// ================= Kernel 2: X = b1 + ea*W1a + sh*B[s]  (GEMM-tiled) =================
__global__ void __launch_bounds__(256) k_X(
    const float* __restrict__ edge_attr, const float* __restrict__ edge_sh,
    const float* __restrict__ mW1, const float* __restrict__ mb1)
{
    __shared__ float eaT[32][132];
    __shared__ float shT[9][132];
    __shared__ float sB[8][576];
    __shared__ float sW1a[32 * 64];
    __shared__ float sb1[64];

    int tid = threadIdx.x;
    int rt = blockIdx.x >> 6, st = blockIdx.x & 63;
    int r0 = rt * 16, s0 = st * 8;

    for (int i = tid; i < 1024; i += 256) {
        int el = i >> 3, k4 = i & 7;
        int rr = el >> 3, ssl = el & 7;
        float4 v = __ldg((const float4*)&edge_attr[((size_t)(r0 + rr) * 512 + s0 + ssl) * 32 + k4 * 4]);
        int e = ssl * 16 + rr;
        eaT[k4*4+0][e] = v.x; eaT[k4*4+1][e] = v.y;
        eaT[k4*4+2][e] = v.z; eaT[k4*4+3][e] = v.w;
    }
    for (int i = tid; i < 1152; i += 256) {
        int rr = i / 72, rem = i % 72;
        int ssl = rem / 9, m = rem % 9;
        float v = __ldg(&edge_sh[((size_t)(r0 + rr) * 512 + s0 + ssl) * 9 + m]);
        shT[m][ssl * 16 + rr] = v;
    }
    for (int i = tid; i < 4608; i += 256) {
        int ssl = i / 576, rem = i % 576;
        sB[ssl][rem] = g_B[(size_t)(s0 + ssl) * 576 + rem];
    }
    for (int i = tid; i < 2048; i += 256) sW1a[i] = mW1[i];
    if (tid < 64) sb1[tid] = mb1[tid];
    __syncthreads();

    int ss = tid >> 5, rg = (tid >> 4) & 1, cg = tid & 15;
    int e0 = ss * 16 + rg * 8, c0 = cg * 4;

    float acc[8][4];
#pragma unroll
    for (int j = 0; j < 8; j++) {
        acc[j][0] = sb1[c0]; acc[j][1] = sb1[c0+1];
        acc[j][2] = sb1[c0+2]; acc[j][3] = sb1[c0+3];
    }
#pragma unroll
    for (int k = 0; k < 32; k++) {
        float4 a0 = *(float4*)&eaT[k][e0];
        float4 a1 = *(float4*)&eaT[k][e0 + 4];
        float4 b  = *(float4*)&sW1a[k * 64 + c0];
        float av[8] = {a0.x,a0.y,a0.z,a0.w,a1.x,a1.y,a1.z,a1.w};
#pragma unroll
        for (int j = 0; j < 8; j++) {
            acc[j][0] += av[j]*b.x; acc[j][1] += av[j]*b.y;
            acc[j][2] += av[j]*b.z; acc[j][3] += av[j]*b.w;
        }
    }
#pragma unroll
    for (int m = 0; m < 9; m++) {
        float4 a0 = *(float4*)&shT[m][e0];
        float4 a1 = *(float4*)&shT[m][e0 + 4];
        float4 b  = *(float4*)&sB[ss][m * 64 + c0];
        float av[8] = {a0.x,a0.y,a0.z,a0.w,a1.x,a1.y,a1.z,a1.w};
#pragma unroll
        for (int j = 0; j < 8; j++) {
            acc[j][0] += av[j]*b.x; acc[j][1] += av[j]*b.y;
            acc[j][2] += av[j]*b.z; acc[j][3] += av[j]*b.w;
        }
    }
#pragma unroll
    for (int j = 0; j < 8; j++) {
        int r = r0 + rg * 8 + j, s = s0 + ss;
        *(float4*)&g_X[((size_t)r * 512 + s) * 64 + c0] =
            make_float4(acc[j][0], acc[j][1], acc[j][2], acc[j][3]);
    }
}

// ================= Kernel 3: logits GEMM per head =================
#define QKS 61
__global__ void __launch_bounds__(256) k_logit()
{
    __shared__ float qs[64 * QKS];
    __shared__ float ks[64 * QKS];
    int tid = threadIdx.x;
    int hh = blockIdx.x >> 6, tile = blockIdx.x & 63;
    int r0 = (tile >> 3) * 64, s0 = (tile & 7) * 64;

    for (int i = tid; i < 960; i += 256) {
        int nl = i / 15, k4 = i % 15;
        float4 vq = *(const float4*)&g_qh[((size_t)(r0 + nl) * H + hh) * 60 + k4 * 4];
        float4 vk = *(const float4*)&g_kh[((size_t)(s0 + nl) * H + hh) * 60 + k4 * 4];
        float* qd = &qs[nl * QKS + k4 * 4];
        float* kd = &ks[nl * QKS + k4 * 4];
        qd[0] = vq.x; qd[1] = vq.y; qd[2] = vq.z; qd[3] = vq.w;
        kd[0] = vk.x; kd[1] = vk.y; kd[2] = vk.z; kd[3] = vk.w;
    }
    __syncthreads();

    int tx = tid & 15, ty = tid >> 4;
    float acc[4][4];
#pragma unroll
    for (int i = 0; i < 4; i++)
#pragma unroll
        for (int j = 0; j < 4; j++) acc[i][j] = 0.f;

    for (int k = 0; k < 60; k++) {
        float a_[4], b_[4];
#pragma unroll
        for (int i = 0; i < 4; i++) a_[i] = qs[(ty * 4 + i) * QKS + k];
#pragma unroll
        for (int j = 0; j < 4; j++) b_[j] = ks[(tx * 4 + j) * QKS + k];
#pragma unroll
        for (int i = 0; i < 4; i++)
#pragma unroll
            for (int j = 0; j < 4; j++) acc[i][j] += a_[i] * b_[j];
    }

    float* base = g_P + (size_t)hh * (N_NODES * N_NODES);
#pragma unroll
    for (int i = 0; i < 4; i++) {
        *(float4*)&base[(size_t)(r0 + ty * 4 + i) * N_NODES + s0 + tx * 4] =
            make_float4(acc[i][0], acc[i][1], acc[i][2], acc[i][3]);
    }
}

// ================= Kernel 4: h1=tanh(X+sh*A[r]); GEMM2; tanh; W3 -> P =================
// One block = one (r, 128-s tile). Flat phases, no outer loop.
#define H1S 132
#define SMEM_MLP ((64*H1S + 1152 + 64*64 + 576 + 512 + 64 + 8) * 4)

__global__ void __launch_bounds__(256, 2) k_mlp(
    const float* __restrict__ edge_sh,
    const float* __restrict__ mW2, const float* __restrict__ mb2,
    const float* __restrict__ mW3, const float* __restrict__ mb3)
{
    extern __shared__ float sm[];
    float* h1T = sm;                    // [64][H1S]  h1 then h2, transposed [c][s]
    float* shs = h1T + 64 * H1S;        // [1152] = 128 edges x 9
    float* sW2 = shs + 1152;            // [64][64]
    float* sA  = sW2 + 4096;            // [9][64]
    float* sW3 = sA + 576;              // [64][8]
    float* sb2 = sW3 + 512;             // [64]
    float* sb3 = sb2 + 64;              // [8]

    int tid = threadIdx.x;
    int r = blockIdx.x >> 2;
    int s0 = (blockIdx.x & 3) * 128;

    for (int i = tid; i < 4096; i += 256) sW2[i] = mW2[i];
    for (int i = tid; i < 576; i += 256) sA[i] = g_A[(size_t)r * 576 + i];
    for (int i = tid; i < 512; i += 256) sW3[i] = mW3[i];
    if (tid < 64) sb2[tid] = mb2[tid];
    if (tid < 8)  sb3[tid] = mb3[tid];

    const float* shg = edge_sh + ((size_t)r * 512 + s0) * 9;
    for (int i = tid; i < 1152; i += 256) shs[i] = __ldg(shg + i);
    __syncthreads();

    // Phase A: h1 = tanh(X + sh*A), store transposed h1T[c][s]
#pragma unroll
    for (int it = 0; it < 2; it++) {
        int item = tid + 256 * it;
        int cq = item & 3, s_l = item >> 2;
        int c0a = cq * 16;
        float acc[16];
        const float4* Xp = (const float4*)&g_X[((size_t)r * 512 + s0 + s_l) * 64 + c0a];
#pragma unroll
        for (int v4 = 0; v4 < 4; v4++) {
            float4 v = Xp[v4];
            acc[v4*4] = v.x; acc[v4*4+1] = v.y; acc[v4*4+2] = v.z; acc[v4*4+3] = v.w;
        }
#pragma unroll
        for (int m = 0; m < 9; m++) {
            float cm = shs[s_l * 9 + m];
#pragma unroll
            for (int jj = 0; jj < 16; jj++)
                acc[jj] += cm * sA[m * 64 + c0a + jj];
        }
#pragma unroll
        for (int jj = 0; jj < 16; jj++)
            h1T[(c0a + jj) * H1S + s_l] = ftanh(acc[jj]);
    }
    __syncthreads();

    // Phase B: GEMM2: acc2[8 s][4 c] over k=0..63
    int sg = tid >> 4, cgi = tid & 15;
    int sb = sg * 8, c0 = cgi * 4;

    float acc2[8][4];
#pragma unroll
    for (int j = 0; j < 8; j++)
#pragma unroll
        for (int cc = 0; cc < 4; cc++) acc2[j][cc] = 0.f;

#pragma unroll
    for (int k = 0; k < 64; k++) {
        float4 a0 = *(float4*)&h1T[k * H1S + sb];
        float4 a1 = *(float4*)&h1T[k * H1S + sb + 4];
        float4 b  = *(float4*)&sW2[k * 64 + c0];
        float av[8] = {a0.x,a0.y,a0.z,a0.w,a1.x,a1.y,a1.z,a1.w};
#pragma unroll
        for (int j = 0; j < 8; j++) {
            acc2[j][0] += av[j]*b.x; acc2[j][1] += av[j]*b.y;
            acc2[j][2] += av[j]*b.z; acc2[j][3] += av[j]*b.w;
        }
    }
    __syncthreads();

    // Phase C: h2 = tanh(acc2 + b2) -> h1T[c][s]
#pragma unroll
    for (int j = 0; j < 8; j++)
#pragma unroll
        for (int cc = 0; cc < 4; cc++)
            h1T[(c0 + cc) * H1S + sb + j] = ftanh(acc2[j][cc] + sb2[c0 + cc]);
    __syncthreads();

    // Phase D: p[s][h] = b3 + sum_c h2[s][c]*W3[c][h]; P += p (coalesced RMW)
#pragma unroll
    for (int i = 0; i < 4; i++) {
        int item = tid + 256 * i;
        int h = item >> 7, s_l = item & 127;
        float p = sb3[h];
#pragma unroll 8
        for (int c = 0; c < 64; c++)
            p += h1T[c * H1S + s_l] * sW3[c * 8 + h];
        float* Pp = &g_P[(size_t)h * (N_NODES * N_NODES) + (size_t)r * 512 + s0 + s_l];
        *Pp += p;
    }
}

// ================= Kernel 5: softmax + aggregation + residual =================
#define SW_STRIDE 520
#define SMEM3_BYTES (4 * 8 * SW_STRIDE * 4)

__device__ __forceinline__ int h_of(int c) {
    if (c < 128) return c >> 4;
    if (c < 320) return ((c - 128) / 3) >> 3;
    return ((c - 320) / 5) >> 2;
}

__global__ void __launch_bounds__(256) k_out(
    const float* __restrict__ node_feat, float* __restrict__ out)
{
    extern __shared__ float sw[];  // [4][8][520]
    int tid = threadIdx.x;
    int r0 = blockIdx.x * 4;

    for (int i = tid; i < 4096; i += 256) {
        int rr = i >> 10, rem = i & 1023;
        int hh = rem >> 7, s4 = rem & 127;
        float4 v = *(const float4*)&g_P[(size_t)hh * (N_NODES * N_NODES) +
                                        (size_t)(r0 + rr) * N_NODES + s4 * 4];
        float* dst = &sw[(rr * 8 + hh) * SW_STRIDE + s4 * 4];
        dst[0] = v.x; dst[1] = v.y; dst[2] = v.z; dst[3] = v.w;
    }
    __syncthreads();

    int wid = tid >> 5, lane = tid & 31;
    for (int p = wid; p < 32; p += 8) {
        float* row = &sw[p * SW_STRIDE];
        float mx = -1e30f;
#pragma unroll
        for (int k = 0; k < 16; k++) mx = fmaxf(mx, row[lane + 32 * k]);
#pragma unroll
        for (int off = 16; off; off >>= 1) mx = fmaxf(mx, __shfl_xor_sync(0xffffffffu, mx, off));
        float sum = 0.f;
#pragma unroll
        for (int k = 0; k < 16; k++) sum += __expf(row[lane + 32 * k] - mx);
#pragma unroll
        for (int off = 16; off; off >>= 1) sum += __shfl_xor_sync(0xffffffffu, sum, off);
        float rinv = __fdividef(1.0f, sum);
#pragma unroll
        for (int k = 0; k < 16; k++) {
            int s = lane + 32 * k;
            row[s] = __expf(row[s] - mx) * rinv;
        }
    }
    __syncthreads();

    for (int c = wid; c < 480; c += 8) {
        int hh = h_of(c);
        const float* vrow = &g_vmT[(size_t)c * N_NODES];
        const float* w0 = &sw[(0 * 8 + hh) * SW_STRIDE];
        const float* w1 = &sw[(1 * 8 + hh) * SW_STRIDE];
        const float* w2 = &sw[(2 * 8 + hh) * SW_STRIDE];
        const float* w3 = &sw[(3 * 8 + hh) * SW_STRIDE];
        float a0 = 0.f, a1 = 0.f, a2 = 0.f, a3 = 0.f;
#pragma unroll
        for (int k = 0; k < 16; k++) {
            int s = k * 32 + lane;
            float vv = vrow[s];
            a0 += w0[s] * vv; a1 += w1[s] * vv; a2 += w2[s] * vv; a3 += w3[s] * vv;
        }
#pragma unroll
        for (int off = 16; off; off >>= 1) {
            a0 += __shfl_xor_sync(0xffffffffu, a0, off);
            a1 += __shfl_xor_sync(0xffffffffu, a1, off);
            a2 += __shfl_xor_sync(0xffffffffu, a2, off);
            a3 += __shfl_xor_sync(0xffffffffu, a3, off);
        }
        if (lane == 0) {
            out[(size_t)(r0 + 0) * 480 + c] = node_feat[(size_t)(r0 + 0) * 480 + c] + a0;
            out[(size_t)(r0 + 1) * 480 + c] = node_feat[(size_t)(r0 + 1) * 480 + c] + a1;
            out[(size_t)(r0 + 2) * 480 + c] = node_feat[(size_t)(r0 + 2) * 480 + c] + a2;
            out[(size_t)(r0 + 3) * 480 + c] = node_feat[(size_t)(r0 + 3) * 480 + c] + a3;
        }
    }
}

// ================= launch =================
extern "C" void kernel_launch(void* const* d_in, const int* in_sizes, int n_in,
                              void* d_out, int out_size)
{
    const float* node_feat = (const float*)d_in[0];
    const float* edge_attr = (const float*)d_in[1];
    const float* edge_sh   = (const float*)d_in[2];
    const float* Wq0 = (const float*)d_in[3];
    const float* Wq1 = (const float*)d_in[4];
    const float* Wq2 = (const float*)d_in[5];
    const float* Wk0 = (const float*)d_in[6];
    const float* Wk1 = (const float*)d_in[7];
    const float* Wk2 = (const float*)d_in[8];
    const float* Wv0 = (const float*)d_in[9];
    const float* Wv1 = (const float*)d_in[10];
    const float* Wv2 = (const float*)d_in[11];
    const float* mW1 = (const float*)d_in[12];
    const float* mb1 = (const float*)d_in[13];
    const float* mW2 = (const float*)d_in[14];
    const float* mb2 = (const float*)d_in[15];
    const float* mW3 = (const float*)d_in[16];
    const float* mb3 = (const float*)d_in[17];
    float* out = (float*)d_out;

    cudaFuncSetAttribute(k_mlp, cudaFuncAttributeMaxDynamicSharedMemorySize, SMEM_MLP);
    cudaFuncSetAttribute(k_out, cudaFuncAttributeMaxDynamicSharedMemorySize, SMEM3_BYTES);

    k_node<<<dim3(128, 2), 256>>>(node_feat, Wq0, Wq1, Wq2, Wk0, Wk1, Wk2, Wv0, Wv1, Wv2, mW1);
    k_X<<<2048, 256>>>(edge_attr, edge_sh, mW1, mb1);
    k_logit<<<512, 256>>>();
    k_mlp<<<2048, 256, SMEM_MLP>>>(edge_sh, mW2, mb2, mW3, mb3);
    k_out<<<128, 256, SMEM3_BYTES>>>(node_feat, out);
}

// round 7
// speedup vs baseline: 1.6855x; 1.1172x over previous
#include <cuda_runtime.h>
#include <cuda_bf16.h>
#include <cstddef>

#define N_NODES 512
#define H 8

// ---------------- device scratch ----------------
__device__ __align__(16) float g_qh[N_NODES * H * 60];
__device__ __align__(16) float g_kh[N_NODES * H * 60];
__device__ __align__(16) float g_A[N_NODES * 9 * 64];
__device__ __align__(16) float g_B[N_NODES * 9 * 64];
__device__ __align__(16) float g_vmT[480 * N_NODES];
__device__ __align__(16) float g_X[(size_t)N_NODES * N_NODES * 64];
__device__ __align__(16) float g_P[(size_t)H * N_NODES * N_NODES];  // planes [h][r][s]

#define CG1 0.5773502691896258f
#define CG2 0.4472135954999579f
#define ATTN_NORM 0.1889822365046136f
#define RS128 0.08838834764831845f
#define RS64  0.125f
#define RS32  0.17677669529663687f

__device__ __forceinline__ float ftanh(float x) {
    return 1.0f - __fdividef(2.0f, __expf(2.0f * x) + 1.0f);
}

__device__ __forceinline__ float f2tf32f(float x) {
    unsigned u;
    asm("cvt.rna.tf32.f32 %0, %1;" : "=r"(u) : "f"(x));
    return __uint_as_float(u);
}

__device__ __forceinline__ void mma_tf32(float* c, const unsigned* a, unsigned b0, unsigned b1) {
    asm volatile(
        "mma.sync.aligned.m16n8k8.row.col.f32.tf32.tf32.f32 "
        "{%0,%1,%2,%3}, {%4,%5,%6,%7}, {%8,%9}, {%0,%1,%2,%3};\n"
        : "+f"(c[0]), "+f"(c[1]), "+f"(c[2]), "+f"(c[3])
        : "r"(a[0]), "r"(a[1]), "r"(a[2]), "r"(a[3]), "r"(b0), "r"(b1));
}

// ================= Kernel 1: per-node precompute =================
__global__ void __launch_bounds__(256) k_node(
    const float* __restrict__ node_feat,
    const float* __restrict__ Wq0, const float* __restrict__ Wq1, const float* __restrict__ Wq2,
    const float* __restrict__ Wk0, const float* __restrict__ Wk1, const float* __restrict__ Wk2,
    const float* __restrict__ Wv0, const float* __restrict__ Wv1, const float* __restrict__ Wv2,
    const float* __restrict__ mW1)
{
    __shared__ float snf[4 * 480];
    int tid = threadIdx.x;
    int n0 = blockIdx.x * 4;

    for (int i = tid; i < 480; i += 256) {
        int nn = i / 120, c4 = i % 120;
        float4 v = *(const float4*)&node_feat[(size_t)(n0 + nn) * 480 + c4 * 4];
        snf[nn * 480 + c4 * 4 + 0] = v.x;
        snf[nn * 480 + c4 * 4 + 1] = v.y;
        snf[nn * 480 + c4 * 4 + 2] = v.z;
        snf[nn * 480 + c4 * 4 + 3] = v.w;
    }
    __syncthreads();

    int gend = 324 * (blockIdx.y + 1);
    for (int g = tid + 324 * blockIdx.y; g < gend; g += 256) {
        int kind, l, m, o, mul, off, mp = 0, stride;
        const float* Wp;
        if (g < 360) {
            int mat = g / 120, gg = g % 120;
            if (gg < 32)      { l = 0; m = 0;              o = gg * 4; }
            else if (gg < 80) { int t = gg - 32; l = 1; o = (t / 3) * 4; m = t % 3; }
            else              { int t = gg - 80; l = 2; o = (t / 5) * 4; m = t % 5; }
            mul = (l == 0) ? 128 : (l == 1) ? 64 : 32;
            off = (l == 0) ? 0 : (l == 1) ? 128 : 320;
            stride = mul;
            if (mat == 0)      Wp = (l == 0) ? Wq0 : (l == 1) ? Wq1 : Wq2;
            else if (mat == 1) Wp = (l == 0) ? Wk0 : (l == 1) ? Wk1 : Wk2;
            else               Wp = (l == 0) ? Wv0 : (l == 1) ? Wv1 : Wv2;
            kind = mat;
        } else {
            int t = g - 360;
            int ab = t / 144, u = t % 144;
            mp = u / 16; o = (u % 16) * 4;
            l = (mp == 0) ? 0 : (mp < 4) ? 1 : 2;
            m = (mp == 0) ? 0 : (mp < 4) ? (mp - 1) : (mp - 4);
            mul = (l == 0) ? 128 : (l == 1) ? 64 : 32;
            off = (l == 0) ? 0 : (l == 1) ? 128 : 320;
            int row = ((l == 0) ? 32 : (l == 1) ? 160 : 224) + ab * 224;
            Wp = mW1 + (size_t)row * 64;
            stride = 64;
            kind = 3 + ab;
        }
        int d = 2 * l + 1;

        float4 a0 = make_float4(0.f,0.f,0.f,0.f), a1 = a0, a2 = a0, a3 = a0;
#pragma unroll 4
        for (int i = 0; i < mul; i++) {
            float4 wv = __ldg((const float4*)&Wp[(size_t)i * stride + o]);
            int col = off + i * d + m;
            float x0 = snf[col], x1 = snf[480 + col], x2 = snf[960 + col], x3 = snf[1440 + col];
            a0.x += x0 * wv.x; a0.y += x0 * wv.y; a0.z += x0 * wv.z; a0.w += x0 * wv.w;
            a1.x += x1 * wv.x; a1.y += x1 * wv.y; a1.z += x1 * wv.z; a1.w += x1 * wv.w;
            a2.x += x2 * wv.x; a2.y += x2 * wv.y; a2.z += x2 * wv.z; a2.w += x2 * wv.w;
            a3.x += x3 * wv.x; a3.y += x3 * wv.y; a3.z += x3 * wv.z; a3.w += x3 * wv.w;
        }

        float rs = (l == 0) ? RS128 : (l == 1) ? RS64 : RS32;
        float cg = (l == 0) ? 1.f   : (l == 1) ? CG1  : CG2;
        float accs[4][4] = {{a0.x,a0.y,a0.z,a0.w},{a1.x,a1.y,a1.z,a1.w},
                            {a2.x,a2.y,a2.z,a2.w},{a3.x,a3.y,a3.z,a3.w}};
#pragma unroll
        for (int nn = 0; nn < 4; nn++) {
            int n = n0 + nn;
#pragma unroll
            for (int oo = 0; oo < 4; oo++) {
                int o_ = o + oo;
                float a = accs[nn][oo];
                if (kind <= 1) {
                    int am = mul >> 3;
                    int hh = o_ / am, oi = o_ % am;
                    int j = (l == 0) ? oi : (l == 1) ? (16 + oi * 3 + m) : (40 + oi * 5 + m);
                    size_t idx = ((size_t)n * H + hh) * 60 + j;
                    if (kind == 0) g_qh[idx] = a * rs * cg * ATTN_NORM;
                    else           g_kh[idx] = a * rs;
                } else if (kind == 2) {
                    int w = (l == 0) ? o_ : (l == 1) ? (128 + o_ * 3 + m) : (320 + o_ * 5 + m);
                    g_vmT[(size_t)w * N_NODES + n] = a * rs;
                } else {
                    float* dst = (kind == 3) ? g_A : g_B;
                    dst[((size_t)n * 9 + mp) * 64 + o_] = a * cg;
                }
            }
        }
    }
}

// ================= Kernel 2: X = b1 + ea*W1a + sh*B[s]  (tf32 tensor GEMM) =================
// Block = (s, 128-r tile). A[128 x 48]: cols 0..31 ea, 32..40 sh, 41..47 zero.
// B[48 x 64]: rows 0..31 W1a, 32..40 B[s], 41..47 zero.
#define XAS 52
#define XBS 68
__global__ void __launch_bounds__(256, 2) k_X(
    const float* __restrict__ edge_attr, const float* __restrict__ edge_sh,
    const float* __restrict__ mW1, const float* __restrict__ mb1)
{
    __shared__ float sAe[128 * XAS];
    __shared__ float sBm[48 * XBS];
    __shared__ float sb1[64];

    int tid = threadIdx.x;
    int s = blockIdx.x >> 2;
    int r0 = (blockIdx.x & 3) * 128;

    for (int i = tid; i < 1024; i += 256) {
        int r_l = i >> 3, k4 = i & 7;
        float4 v = __ldg((const float4*)&edge_attr[((size_t)(r0 + r_l) * 512 + s) * 32 + k4 * 4]);
        float* d = &sAe[r_l * XAS + k4 * 4];
        d[0] = f2tf32f(v.x); d[1] = f2tf32f(v.y); d[2] = f2tf32f(v.z); d[3] = f2tf32f(v.w);
    }
    for (int i = tid; i < 1152; i += 256) {
        int r_l = i / 9, m = i % 9;
        sAe[r_l * XAS + 32 + m] = f2tf32f(__ldg(&edge_sh[((size_t)(r0 + r_l) * 512 + s) * 9 + m]));
    }
    for (int i = tid; i < 128 * 7; i += 256) {
        int r_l = i / 7, c = 41 + i % 7;
        sAe[r_l * XAS + c] = 0.f;
    }
    for (int i = tid; i < 2048; i += 256) {
        int k = i >> 6, n = i & 63;
        sBm[k * XBS + n] = f2tf32f(mW1[i]);
    }
    for (int i = tid; i < 576; i += 256) {
        int m = i / 64, n = i % 64;
        sBm[(32 + m) * XBS + n] = f2tf32f(g_B[(size_t)s * 576 + i]);
    }
    for (int i = tid; i < 7 * 64; i += 256) {
        sBm[(41 + i / 64) * XBS + (i % 64)] = 0.f;
    }
    if (tid < 64) sb1[tid] = mb1[tid];
    __syncthreads();

    int w = tid >> 5, lane = tid & 31;
    int g = lane >> 2, t = lane & 3;
    int row0 = w * 16 + g;

    float acc[8][4];
#pragma unroll
    for (int nt = 0; nt < 8; nt++)
#pragma unroll
        for (int cc = 0; cc < 4; cc++) acc[nt][cc] = 0.f;

#pragma unroll
    for (int ksi = 0; ksi < 6; ksi++) {
        int col = ksi * 8 + t;
        unsigned a[4];
        a[0] = __float_as_uint(sAe[row0 * XAS + col]);
        a[1] = __float_as_uint(sAe[(row0 + 8) * XAS + col]);
        a[2] = __float_as_uint(sAe[row0 * XAS + col + 4]);
        a[3] = __float_as_uint(sAe[(row0 + 8) * XAS + col + 4]);
#pragma unroll
        for (int nt = 0; nt < 8; nt++) {
            unsigned b0 = __float_as_uint(sBm[(ksi * 8 + t) * XBS + nt * 8 + g]);
            unsigned b1 = __float_as_uint(sBm[(ksi * 8 + t + 4) * XBS + nt * 8 + g]);
            mma_tf32(acc[nt], a, b0, b1);
        }
    }

#pragma unroll
    for (int nt = 0; nt < 8; nt++) {
        int col0 = nt * 8 + 2 * t;
        float b0 = sb1[col0], b1v = sb1[col0 + 1];
        *(float2*)&g_X[((size_t)(r0 + row0) * 512 + s) * 64 + col0] =
            make_float2(acc[nt][0] + b0, acc[nt][1] + b1v);
        *(float2*)&g_X[((size_t)(r0 + row0 + 8) * 512 + s) * 64 + col0] =
            make_float2(acc[nt][2] + b0, acc[nt][3] + b1v);
    }
}

// ================= Kernel 3: logits GEMM per head =================
#define QKS 61
__global__ void __launch_bounds__(256) k_logit()
{
    __shared__ float qs[64 * QKS];
    __shared__ float ks[64 * QKS];
    int tid = threadIdx.x;
    int hh = blockIdx.x >> 6, tile = blockIdx.x & 63;
    int r0 = (tile >> 3) * 64, s0 = (tile & 7) * 64;

    for (int i = tid; i < 960; i += 256) {
        int nl = i / 15, k4 = i % 15;
        float4 vq = *(const float4*)&g_qh[((size_t)(r0 + nl) * H + hh) * 60 + k4 * 4];
        float4 vk = *(const float4*)&g_kh[((size_t)(s0 + nl) * H + hh) * 60 + k4 * 4];
        float* qd = &qs[nl * QKS + k4 * 4];
        float* kd = &ks[nl * QKS + k4 * 4];
        qd[0] = vq.x; qd[1] = vq.y; qd[2] = vq.z; qd[3] = vq.w;
        kd[0] = vk.x; kd[1] = vk.y; kd[2] = vk.z; kd[3] = vk.w;
    }
    __syncthreads();

    int tx = tid & 15, ty = tid >> 4;
    float acc[4][4];
#pragma unroll
    for (int i = 0; i < 4; i++)
#pragma unroll
        for (int j = 0; j < 4; j++) acc[i][j] = 0.f;

    for (int k = 0; k < 60; k++) {
        float a_[4], b_[4];
#pragma unroll
        for (int i = 0; i < 4; i++) a_[i] = qs[(ty * 4 + i) * QKS + k];
#pragma unroll
        for (int j = 0; j < 4; j++) b_[j] = ks[(tx * 4 + j) * QKS + k];
#pragma unroll
        for (int i = 0; i < 4; i++)
#pragma unroll
            for (int j = 0; j < 4; j++) acc[i][j] += a_[i] * b_[j];
    }

    float* base = g_P + (size_t)hh * (N_NODES * N_NODES);
#pragma unroll
    for (int i = 0; i < 4; i++) {
        *(float4*)&base[(size_t)(r0 + ty * 4 + i) * N_NODES + s0 + tx * 4] =
            make_float4(acc[i][0], acc[i][1], acc[i][2], acc[i][3]);
    }
}

// ================= Kernel 4: h1=tanh(X+sh*A[r]); tf32 GEMM2; tanh; W3 -> P =================
#define MS 68      // [s][k] tf32 A stride
#define H2S 132    // [c][s] h2 stride
// smem floats: sh1 128*68 + sW2 64*68 + h2T 64*132 + shs 1152 + sA 576 + sW3 512 + sb2 64 + sb3 8
#define SMEM_MLP ((128*MS + 64*MS + 64*H2S + 1152 + 576 + 512 + 64 + 8) * 4)

__global__ void __launch_bounds__(256, 2) k_mlp(
    const float* __restrict__ edge_sh,
    const float* __restrict__ mW2, const float* __restrict__ mb2,
    const float* __restrict__ mW3, const float* __restrict__ mb3)
{
    extern __shared__ float sm[];
    float* sh1 = sm;                    // [128][MS]  h1 as tf32 bits, row=s col=k
    float* sW2 = sh1 + 128 * MS;        // [64][MS]   W2 tf32, row=k col=n
    float* h2T = sW2 + 64 * MS;         // [64][H2S]  h2, [c][s]
    float* shs = h2T + 64 * H2S;        // [1152]
    float* sA  = shs + 1152;            // [9][64]
    float* sW3 = sA + 576;              // [64][8]
    float* sb2 = sW3 + 512;
    float* sb3 = sb2 + 64;

    int tid = threadIdx.x;
    int r = blockIdx.x >> 2;
    int s0 = (blockIdx.x & 3) * 128;

    for (int i = tid; i < 4096; i += 256) {
        int k = i >> 6, n = i & 63;
        sW2[k * MS + n] = f2tf32f(mW2[i]);
    }
    for (int i = tid; i < 576; i += 256) sA[i] = g_A[(size_t)r * 576 + i];
    for (int i = tid; i < 512; i += 256) sW3[i] = mW3[i];
    if (tid < 64) sb2[tid] = mb2[tid];
    if (tid < 8)  sb3[tid] = mb3[tid];

    const float* shg = edge_sh + ((size_t)r * 512 + s0) * 9;
    for (int i = tid; i < 1152; i += 256) shs[i] = __ldg(shg + i);
    __syncthreads();

    // Phase A: h1 = tanh(X + sh*A) -> sh1[s][k] (tf32 bits)
#pragma unroll
    for (int it = 0; it < 2; it++) {
        int item = tid + 256 * it;
        int cq = item & 3, s_l = item >> 2;
        int c0a = cq * 16;
        float acc[16];
        const float4* Xp = (const float4*)&g_X[((size_t)r * 512 + s0 + s_l) * 64 + c0a];
#pragma unroll
        for (int v4 = 0; v4 < 4; v4++) {
            float4 v = Xp[v4];
            acc[v4*4] = v.x; acc[v4*4+1] = v.y; acc[v4*4+2] = v.z; acc[v4*4+3] = v.w;
        }
#pragma unroll
        for (int m = 0; m < 9; m++) {
            float cm = shs[s_l * 9 + m];
#pragma unroll
            for (int jj = 0; jj < 16; jj++)
                acc[jj] += cm * sA[m * 64 + c0a + jj];
        }
#pragma unroll
        for (int jj = 0; jj < 16; jj++)
            sh1[s_l * MS + c0a + jj] = f2tf32f(ftanh(acc[jj]));
    }
    __syncthreads();

    // Phase B: tensor GEMM2: warp w = rows [w*16, w*16+16), all 64 cols
    int w = tid >> 5, lane = tid & 31;
    int g = lane >> 2, t = lane & 3;
    int row0 = w * 16 + g;

    float acc2[8][4];
#pragma unroll
    for (int nt = 0; nt < 8; nt++)
#pragma unroll
        for (int cc = 0; cc < 4; cc++) acc2[nt][cc] = 0.f;

#pragma unroll
    for (int ksi = 0; ksi < 8; ksi++) {
        int col = ksi * 8 + t;
        unsigned a[4];
        a[0] = __float_as_uint(sh1[row0 * MS + col]);
        a[1] = __float_as_uint(sh1[(row0 + 8) * MS + col]);
        a[2] = __float_as_uint(sh1[row0 * MS + col + 4]);
        a[3] = __float_as_uint(sh1[(row0 + 8) * MS + col + 4]);
#pragma unroll
        for (int nt = 0; nt < 8; nt++) {
            unsigned b0 = __float_as_uint(sW2[(ksi * 8 + t) * MS + nt * 8 + g]);
            unsigned b1 = __float_as_uint(sW2[(ksi * 8 + t + 4) * MS + nt * 8 + g]);
            mma_tf32(acc2[nt], a, b0, b1);
        }
    }

    // Phase C: h2 = tanh(acc2 + b2) -> h2T[c][s]
#pragma unroll
    for (int nt = 0; nt < 8; nt++) {
        int col0 = nt * 8 + 2 * t;
        float b0 = sb2[col0], b1v = sb2[col0 + 1];
        h2T[col0 * H2S + row0]           = ftanh(acc2[nt][0] + b0);
        h2T[(col0 + 1) * H2S + row0]     = ftanh(acc2[nt][1] + b1v);
        h2T[col0 * H2S + row0 + 8]       = ftanh(acc2[nt][2] + b0);
        h2T[(col0 + 1) * H2S + row0 + 8] = ftanh(acc2[nt][3] + b1v);
    }
    __syncthreads();

    // Phase D: p[s][h] = b3 + sum_c h2[s][c]*W3[c][h]; P += p (coalesced RMW)
#pragma unroll
    for (int i = 0; i < 4; i++) {
        int item = tid + 256 * i;
        int h = item >> 7, s_l = item & 127;
        float p = sb3[h];
#pragma unroll 8
        for (int c = 0; c < 64; c++)
            p += h2T[c * H2S + s_l] * sW3[c * 8 + h];
        float* Pp = &g_P[(size_t)h * (N_NODES * N_NODES) + (size_t)r * 512 + s0 + s_l];
        *Pp += p;
    }
}

// ================= Kernel 5: softmax + aggregation + residual =================
#define SW_STRIDE 520
#define SMEM3_BYTES (4 * 8 * SW_STRIDE * 4)

__device__ __forceinline__ int h_of(int c) {
    if (c < 128) return c >> 4;
    if (c < 320) return ((c - 128) / 3) >> 3;
    return ((c - 320) / 5) >> 2;
}

__global__ void __launch_bounds__(256) k_out(
    const float* __restrict__ node_feat, float* __restrict__ out)
{
    extern __shared__ float sw[];  // [4][8][520]
    int tid = threadIdx.x;
    int r0 = blockIdx.x * 4;

    for (int i = tid; i < 4096; i += 256) {
        int rr = i >> 10, rem = i & 1023;
        int hh = rem >> 7, s4 = rem & 127;
        float4 v = *(const float4*)&g_P[(size_t)hh * (N_NODES * N_NODES) +
                                        (size_t)(r0 + rr) * N_NODES + s4 * 4];
        float* dst = &sw[(rr * 8 + hh) * SW_STRIDE + s4 * 4];
        dst[0] = v.x; dst[1] = v.y; dst[2] = v.z; dst[3] = v.w;
    }
    __syncthreads();

    int wid = tid >> 5, lane = tid & 31;
    for (int p = wid; p < 32; p += 8) {
        float* row = &sw[p * SW_STRIDE];
        float mx = -1e30f;
#pragma unroll
        for (int k = 0; k < 16; k++) mx = fmaxf(mx, row[lane + 32 * k]);
#pragma unroll
        for (int off = 16; off; off >>= 1) mx = fmaxf(mx, __shfl_xor_sync(0xffffffffu, mx, off));
        float sum = 0.f;
#pragma unroll
        for (int k = 0; k < 16; k++) sum += __expf(row[lane + 32 * k] - mx);
#pragma unroll
        for (int off = 16; off; off >>= 1) sum += __shfl_xor_sync(0xffffffffu, sum, off);
        float rinv = __fdividef(1.0f, sum);
#pragma unroll
        for (int k = 0; k < 16; k++) {
            int s = lane + 32 * k;
            row[s] = __expf(row[s] - mx) * rinv;
        }
    }
    __syncthreads();

    for (int c = wid; c < 480; c += 8) {
        int hh = h_of(c);
        const float* vrow = &g_vmT[(size_t)c * N_NODES];
        const float* w0 = &sw[(0 * 8 + hh) * SW_STRIDE];
        const float* w1 = &sw[(1 * 8 + hh) * SW_STRIDE];
        const float* w2 = &sw[(2 * 8 + hh) * SW_STRIDE];
        const float* w3 = &sw[(3 * 8 + hh) * SW_STRIDE];
        float a0 = 0.f, a1 = 0.f, a2 = 0.f, a3 = 0.f;
#pragma unroll
        for (int k = 0; k < 16; k++) {
            int s = k * 32 + lane;
            float vv = vrow[s];
            a0 += w0[s] * vv; a1 += w1[s] * vv; a2 += w2[s] * vv; a3 += w3[s] * vv;
        }
#pragma unroll
        for (int off = 16; off; off >>= 1) {
            a0 += __shfl_xor_sync(0xffffffffu, a0, off);
            a1 += __shfl_xor_sync(0xffffffffu, a1, off);
            a2 += __shfl_xor_sync(0xffffffffu, a2, off);
            a3 += __shfl_xor_sync(0xffffffffu, a3, off);
        }
        if (lane == 0) {
            out[(size_t)(r0 + 0) * 480 + c] = node_feat[(size_t)(r0 + 0) * 480 + c] + a0;
            out[(size_t)(r0 + 1) * 480 + c] = node_feat[(size_t)(r0 + 1) * 480 + c] + a1;
            out[(size_t)(r0 + 2) * 480 + c] = node_feat[(size_t)(r0 + 2) * 480 + c] + a2;
            out[(size_t)(r0 + 3) * 480 + c] = node_feat[(size_t)(r0 + 3) * 480 + c] + a3;
        }
    }
}

// ================= launch =================
extern "C" void kernel_launch(void* const* d_in, const int* in_sizes, int n_in,
                              void* d_out, int out_size)
{
    const float* node_feat = (const float*)d_in[0];
    const float* edge_attr = (const float*)d_in[1];
    const float* edge_sh   = (const float*)d_in[2];
    const float* Wq0 = (const float*)d_in[3];
    const float* Wq1 = (const float*)d_in[4];
    const float* Wq2 = (const float*)d_in[5];
    const float* Wk0 = (const float*)d_in[6];
    const float* Wk1 = (const float*)d_in[7];
    const float* Wk2 = (const float*)d_in[8];
    const float* Wv0 = (const float*)d_in[9];
    const float* Wv1 = (const float*)d_in[10];
    const float* Wv2 = (const float*)d_in[11];
    const float* mW1 = (const float*)d_in[12];
    const float* mb1 = (const float*)d_in[13];
    const float* mW2 = (const float*)d_in[14];
    const float* mb2 = (const float*)d_in[15];
    const float* mW3 = (const float*)d_in[16];
    const float* mb3 = (const float*)d_in[17];
    float* out = (float*)d_out;

    cudaFuncSetAttribute(k_mlp, cudaFuncAttributeMaxDynamicSharedMemorySize, SMEM_MLP);
    cudaFuncSetAttribute(k_out, cudaFuncAttributeMaxDynamicSharedMemorySize, SMEM3_BYTES);

    k_node<<<dim3(128, 2), 256>>>(node_feat, Wq0, Wq1, Wq2, Wk0, Wk1, Wk2, Wv0, Wv1, Wv2, mW1);
    k_X<<<2048, 256>>>(edge_attr, edge_sh, mW1, mb1);
    k_logit<<<512, 256>>>();
    k_mlp<<<2048, 256, SMEM_MLP>>>(edge_sh, mW2, mb2, mW3, mb3);
    k_out<<<128, 256, SMEM3_BYTES>>>(node_feat, out);
}

// round 8
// speedup vs baseline: 1.8543x; 1.1001x over previous
#include <cuda_runtime.h>
#include <cuda_bf16.h>
#include <cstddef>

#define N_NODES 512
#define H 8

// ---------------- device scratch ----------------
__device__ __align__(16) float g_qh[N_NODES * H * 60];
__device__ __align__(16) float g_kh[N_NODES * H * 60];
__device__ __align__(16) float g_A[N_NODES * 9 * 64];
__device__ __align__(16) float g_B[N_NODES * 9 * 64];
__device__ __align__(16) float g_vmT[480 * N_NODES];
__device__ __align__(16) float g_X[(size_t)N_NODES * N_NODES * 64];
__device__ __align__(16) float g_P[(size_t)H * N_NODES * N_NODES];  // planes [h][r][s]

#define CG1 0.5773502691896258f
#define CG2 0.4472135954999579f
#define ATTN_NORM 0.1889822365046136f
#define RS128 0.08838834764831845f
#define RS64  0.125f
#define RS32  0.17677669529663687f

__device__ __forceinline__ float ftanh(float x) {
    return 1.0f - __fdividef(2.0f, __expf(2.0f * x) + 1.0f);
}

__device__ __forceinline__ float f2tf32f(float x) {
    unsigned u;
    asm("cvt.rna.tf32.f32 %0, %1;" : "=r"(u) : "f"(x));
    return __uint_as_float(u);
}

__device__ __forceinline__ void mma_tf32(float* c, const unsigned* a, unsigned b0, unsigned b1) {
    asm volatile(
        "mma.sync.aligned.m16n8k8.row.col.f32.tf32.tf32.f32 "
        "{%0,%1,%2,%3}, {%4,%5,%6,%7}, {%8,%9}, {%0,%1,%2,%3};\n"
        : "+f"(c[0]), "+f"(c[1]), "+f"(c[2]), "+f"(c[3])
        : "r"(a[0]), "r"(a[1]), "r"(a[2]), "r"(a[3]), "r"(b0), "r"(b1));
}

// ================= Kernel 1: per-node precompute =================
__global__ void __launch_bounds__(256) k_node(
    const float* __restrict__ node_feat,
    const float* __restrict__ Wq0, const float* __restrict__ Wq1, const float* __restrict__ Wq2,
    const float* __restrict__ Wk0, const float* __restrict__ Wk1, const float* __restrict__ Wk2,
    const float* __restrict__ Wv0, const float* __restrict__ Wv1, const float* __restrict__ Wv2,
    const float* __restrict__ mW1)
{
    __shared__ float snf[4 * 480];
    int tid = threadIdx.x;
    int n0 = blockIdx.x * 4;

    for (int i = tid; i < 480; i += 256) {
        int nn = i / 120, c4 = i % 120;
        float4 v = *(const float4*)&node_feat[(size_t)(n0 + nn) * 480 + c4 * 4];
        snf[nn * 480 + c4 * 4 + 0] = v.x;
        snf[nn * 480 + c4 * 4 + 1] = v.y;
        snf[nn * 480 + c4 * 4 + 2] = v.z;
        snf[nn * 480 + c4 * 4 + 3] = v.w;
    }
    __syncthreads();

    int gend = 324 * (blockIdx.y + 1);
    for (int g = tid + 324 * blockIdx.y; g < gend; g += 256) {
        int kind, l, m, o, mul, off, mp = 0, stride;
        const float* Wp;
        if (g < 360) {
            int mat = g / 120, gg = g % 120;
            if (gg < 32)      { l = 0; m = 0;              o = gg * 4; }
            else if (gg < 80) { int t = gg - 32; l = 1; o = (t / 3) * 4; m = t % 3; }
            else              { int t = gg - 80; l = 2; o = (t / 5) * 4; m = t % 5; }
            mul = (l == 0) ? 128 : (l == 1) ? 64 : 32;
            off = (l == 0) ? 0 : (l == 1) ? 128 : 320;
            stride = mul;
            if (mat == 0)      Wp = (l == 0) ? Wq0 : (l == 1) ? Wq1 : Wq2;
            else if (mat == 1) Wp = (l == 0) ? Wk0 : (l == 1) ? Wk1 : Wk2;
            else               Wp = (l == 0) ? Wv0 : (l == 1) ? Wv1 : Wv2;
            kind = mat;
        } else {
            int t = g - 360;
            int ab = t / 144, u = t % 144;
            mp = u / 16; o = (u % 16) * 4;
            l = (mp == 0) ? 0 : (mp < 4) ? 1 : 2;
            m = (mp == 0) ? 0 : (mp < 4) ? (mp - 1) : (mp - 4);
            mul = (l == 0) ? 128 : (l == 1) ? 64 : 32;
            off = (l == 0) ? 0 : (l == 1) ? 128 : 320;
            int row = ((l == 0) ? 32 : (l == 1) ? 160 : 224) + ab * 224;
            Wp = mW1 + (size_t)row * 64;
            stride = 64;
            kind = 3 + ab;
        }
        int d = 2 * l + 1;

        float4 a0 = make_float4(0.f,0.f,0.f,0.f), a1 = a0, a2 = a0, a3 = a0;
#pragma unroll 4
        for (int i = 0; i < mul; i++) {
            float4 wv = __ldg((const float4*)&Wp[(size_t)i * stride + o]);
            int col = off + i * d + m;
            float x0 = snf[col], x1 = snf[480 + col], x2 = snf[960 + col], x3 = snf[1440 + col];
            a0.x += x0 * wv.x; a0.y += x0 * wv.y; a0.z += x0 * wv.z; a0.w += x0 * wv.w;
            a1.x += x1 * wv.x; a1.y += x1 * wv.y; a1.z += x1 * wv.z; a1.w += x1 * wv.w;
            a2.x += x2 * wv.x; a2.y += x2 * wv.y; a2.z += x2 * wv.z; a2.w += x2 * wv.w;
            a3.x += x3 * wv.x; a3.y += x3 * wv.y; a3.z += x3 * wv.z; a3.w += x3 * wv.w;
        }

        float rs = (l == 0) ? RS128 : (l == 1) ? RS64 : RS32;
        float cg = (l == 0) ? 1.f   : (l == 1) ? CG1  : CG2;
        float accs[4][4] = {{a0.x,a0.y,a0.z,a0.w},{a1.x,a1.y,a1.z,a1.w},
                            {a2.x,a2.y,a2.z,a2.w},{a3.x,a3.y,a3.z,a3.w}};
#pragma unroll
        for (int nn = 0; nn < 4; nn++) {
            int n = n0 + nn;
#pragma unroll
            for (int oo = 0; oo < 4; oo++) {
                int o_ = o + oo;
                float a = accs[nn][oo];
                if (kind <= 1) {
                    int am = mul >> 3;
                    int hh = o_ / am, oi = o_ % am;
                    int j = (l == 0) ? oi : (l == 1) ? (16 + oi * 3 + m) : (40 + oi * 5 + m);
                    size_t idx = ((size_t)n * H + hh) * 60 + j;
                    if (kind == 0) g_qh[idx] = a * rs * cg * ATTN_NORM;
                    else           g_kh[idx] = a * rs;
                } else if (kind == 2) {
                    int w = (l == 0) ? o_ : (l == 1) ? (128 + o_ * 3 + m) : (320 + o_ * 5 + m);
                    g_vmT[(size_t)w * N_NODES + n] = a * rs;
                } else {
                    float* dst = (kind == 3) ? g_A : g_B;
                    dst[((size_t)n * 9 + mp) * 64 + o_] = a * cg;
                }
            }
        }
    }
}

// ================= Kernel 2: X = b1 + ea*W1a + sh*B[s]  (tf32 tensor GEMM) =================
#define XAS 52
#define XBS 68
__global__ void __launch_bounds__(256, 2) k_X(
    const float* __restrict__ edge_attr, const float* __restrict__ edge_sh,
    const float* __restrict__ mW1, const float* __restrict__ mb1)
{
    __shared__ float sAe[128 * XAS];
    __shared__ float sBm[48 * XBS];
    __shared__ float sb1[64];

    int tid = threadIdx.x;
    int s = blockIdx.x >> 2;
    int r0 = (blockIdx.x & 3) * 128;

    for (int i = tid; i < 1024; i += 256) {
        int r_l = i >> 3, k4 = i & 7;
        float4 v = __ldg((const float4*)&edge_attr[((size_t)(r0 + r_l) * 512 + s) * 32 + k4 * 4]);
        float* d = &sAe[r_l * XAS + k4 * 4];
        d[0] = f2tf32f(v.x); d[1] = f2tf32f(v.y); d[2] = f2tf32f(v.z); d[3] = f2tf32f(v.w);
    }
    for (int i = tid; i < 1152; i += 256) {
        int r_l = i / 9, m = i % 9;
        sAe[r_l * XAS + 32 + m] = f2tf32f(__ldg(&edge_sh[((size_t)(r0 + r_l) * 512 + s) * 9 + m]));
    }
    for (int i = tid; i < 128 * 7; i += 256) {
        int r_l = i / 7, c = 41 + i % 7;
        sAe[r_l * XAS + c] = 0.f;
    }
    for (int i = tid; i < 2048; i += 256) {
        int k = i >> 6, n = i & 63;
        sBm[k * XBS + n] = f2tf32f(mW1[i]);
    }
    for (int i = tid; i < 576; i += 256) {
        int m = i / 64, n = i % 64;
        sBm[(32 + m) * XBS + n] = f2tf32f(g_B[(size_t)s * 576 + i]);
    }
    for (int i = tid; i < 7 * 64; i += 256) {
        sBm[(41 + i / 64) * XBS + (i % 64)] = 0.f;
    }
    if (tid < 64) sb1[tid] = mb1[tid];
    __syncthreads();

    int w = tid >> 5, lane = tid & 31;
    int g = lane >> 2, t = lane & 3;
    int row0 = w * 16 + g;

    float acc[8][4];
#pragma unroll
    for (int nt = 0; nt < 8; nt++)
#pragma unroll
        for (int cc = 0; cc < 4; cc++) acc[nt][cc] = 0.f;

#pragma unroll
    for (int ksi = 0; ksi < 6; ksi++) {
        int col = ksi * 8 + t;
        unsigned a[4];
        a[0] = __float_as_uint(sAe[row0 * XAS + col]);
        a[1] = __float_as_uint(sAe[(row0 + 8) * XAS + col]);
        a[2] = __float_as_uint(sAe[row0 * XAS + col + 4]);
        a[3] = __float_as_uint(sAe[(row0 + 8) * XAS + col + 4]);
#pragma unroll
        for (int nt = 0; nt < 8; nt++) {
            unsigned b0 = __float_as_uint(sBm[(ksi * 8 + t) * XBS + nt * 8 + g]);
            unsigned b1 = __float_as_uint(sBm[(ksi * 8 + t + 4) * XBS + nt * 8 + g]);
            mma_tf32(acc[nt], a, b0, b1);
        }
    }

#pragma unroll
    for (int nt = 0; nt < 8; nt++) {
        int col0 = nt * 8 + 2 * t;
        float b0 = sb1[col0], b1v = sb1[col0 + 1];
        *(float2*)&g_X[((size_t)(r0 + row0) * 512 + s) * 64 + col0] =
            make_float2(acc[nt][0] + b0, acc[nt][1] + b1v);
        *(float2*)&g_X[((size_t)(r0 + row0 + 8) * 512 + s) * 64 + col0] =
            make_float2(acc[nt][2] + b0, acc[nt][3] + b1v);
    }
}

// ================= Kernel 3: logits GEMM per head =================
#define QKS 61
__global__ void __launch_bounds__(256) k_logit()
{
    __shared__ float qs[64 * QKS];
    __shared__ float ks[64 * QKS];
    int tid = threadIdx.x;
    int hh = blockIdx.x >> 6, tile = blockIdx.x & 63;
    int r0 = (tile >> 3) * 64, s0 = (tile & 7) * 64;

    for (int i = tid; i < 960; i += 256) {
        int nl = i / 15, k4 = i % 15;
        float4 vq = *(const float4*)&g_qh[((size_t)(r0 + nl) * H + hh) * 60 + k4 * 4];
        float4 vk = *(const float4*)&g_kh[((size_t)(s0 + nl) * H + hh) * 60 + k4 * 4];
        float* qd = &qs[nl * QKS + k4 * 4];
        float* kd = &ks[nl * QKS + k4 * 4];
        qd[0] = vq.x; qd[1] = vq.y; qd[2] = vq.z; qd[3] = vq.w;
        kd[0] = vk.x; kd[1] = vk.y; kd[2] = vk.z; kd[3] = vk.w;
    }
    __syncthreads();

    int tx = tid & 15, ty = tid >> 4;
    float acc[4][4];
#pragma unroll
    for (int i = 0; i < 4; i++)
#pragma unroll
        for (int j = 0; j < 4; j++) acc[i][j] = 0.f;

    for (int k = 0; k < 60; k++) {
        float a_[4], b_[4];
#pragma unroll
        for (int i = 0; i < 4; i++) a_[i] = qs[(ty * 4 + i) * QKS + k];
#pragma unroll
        for (int j = 0; j < 4; j++) b_[j] = ks[(tx * 4 + j) * QKS + k];
#pragma unroll
        for (int i = 0; i < 4; i++)
#pragma unroll
            for (int j = 0; j < 4; j++) acc[i][j] += a_[i] * b_[j];
    }

    float* base = g_P + (size_t)hh * (N_NODES * N_NODES);
#pragma unroll
    for (int i = 0; i < 4; i++) {
        *(float4*)&base[(size_t)(r0 + ty * 4 + i) * N_NODES + s0 + tx * 4] =
            make_float4(acc[i][0], acc[i][1], acc[i][2], acc[i][3]);
    }
}

// ================= Kernel 4: h1=tanh(X+sh*A[r]); tf32 GEMM2; register epilogue -> P ========
#define MS 68      // [s][k] tf32 A stride
// smem floats: sh1 128*68 + sW2 64*68 + shs 1152 + sA 576 + sW3 512 + sb2 64 + sb3 8
#define SMEM_MLP ((128*MS + 64*MS + 1152 + 576 + 512 + 64 + 8) * 4)

__global__ void __launch_bounds__(256, 3) k_mlp(
    const float* __restrict__ edge_sh,
    const float* __restrict__ mW2, const float* __restrict__ mb2,
    const float* __restrict__ mW3, const float* __restrict__ mb3)
{
    extern __shared__ float sm[];
    float* sh1 = sm;                    // [128][MS]  h1 as tf32 bits, row=s col=k
    float* sW2 = sh1 + 128 * MS;        // [64][MS]   W2 tf32, row=k col=n
    float* shs = sW2 + 64 * MS;         // [1152]
    float* sA  = shs + 1152;            // [9][64]
    float* sW3 = sA + 576;              // [64][8]
    float* sb2 = sW3 + 512;
    float* sb3 = sb2 + 64;

    int tid = threadIdx.x;
    int r = blockIdx.x >> 2;
    int s0 = (blockIdx.x & 3) * 128;

    for (int i = tid; i < 4096; i += 256) {
        int k = i >> 6, n = i & 63;
        sW2[k * MS + n] = f2tf32f(mW2[i]);
    }
    for (int i = tid; i < 576; i += 256) sA[i] = g_A[(size_t)r * 576 + i];
    for (int i = tid; i < 512; i += 256) sW3[i] = mW3[i];
    if (tid < 64) sb2[tid] = mb2[tid];
    if (tid < 8)  sb3[tid] = mb3[tid];

    const float* shg = edge_sh + ((size_t)r * 512 + s0) * 9;
    for (int i = tid; i < 1152; i += 256) shs[i] = __ldg(shg + i);
    __syncthreads();

    // Phase A: h1 = tanh(X + sh*A) -> sh1[s][k] (tf32 bits), float4 everywhere
#pragma unroll
    for (int it = 0; it < 2; it++) {
        int item = tid + 256 * it;
        int cq = item & 3, s_l = item >> 2;
        int c0a = cq * 16;
        float4 acc[4];
        const float4* Xp = (const float4*)&g_X[((size_t)r * 512 + s0 + s_l) * 64 + c0a];
#pragma unroll
        for (int v4 = 0; v4 < 4; v4++) acc[v4] = Xp[v4];
#pragma unroll
        for (int m = 0; m < 9; m++) {
            float cm = shs[s_l * 9 + m];
            const float4* Ap = (const float4*)&sA[m * 64 + c0a];
#pragma unroll
            for (int v4 = 0; v4 < 4; v4++) {
                float4 w = Ap[v4];
                acc[v4].x += cm * w.x; acc[v4].y += cm * w.y;
                acc[v4].z += cm * w.z; acc[v4].w += cm * w.w;
            }
        }
        float* drow = &sh1[s_l * MS + c0a];
#pragma unroll
        for (int v4 = 0; v4 < 4; v4++) {
            float4 o;
            o.x = f2tf32f(ftanh(acc[v4].x));
            o.y = f2tf32f(ftanh(acc[v4].y));
            o.z = f2tf32f(ftanh(acc[v4].z));
            o.w = f2tf32f(ftanh(acc[v4].w));
            *(float4*)&drow[v4 * 4] = o;
        }
    }
    __syncthreads();

    // Phase B: tensor GEMM2: warp w = rows [w*16, w*16+16), all 64 cols
    int w = tid >> 5, lane = tid & 31;
    int g = lane >> 2, t = lane & 3;
    int row0 = w * 16 + g;

    float acc2[8][4];
#pragma unroll
    for (int nt = 0; nt < 8; nt++)
#pragma unroll
        for (int cc = 0; cc < 4; cc++) acc2[nt][cc] = 0.f;

#pragma unroll
    for (int ksi = 0; ksi < 8; ksi++) {
        int col = ksi * 8 + t;
        unsigned a[4];
        a[0] = __float_as_uint(sh1[row0 * MS + col]);
        a[1] = __float_as_uint(sh1[(row0 + 8) * MS + col]);
        a[2] = __float_as_uint(sh1[row0 * MS + col + 4]);
        a[3] = __float_as_uint(sh1[(row0 + 8) * MS + col + 4]);
#pragma unroll
        for (int nt = 0; nt < 8; nt++) {
            unsigned b0 = __float_as_uint(sW2[(ksi * 8 + t) * MS + nt * 8 + g]);
            unsigned b1 = __float_as_uint(sW2[(ksi * 8 + t + 4) * MS + nt * 8 + g]);
            mma_tf32(acc2[nt], a, b0, b1);
        }
    }

    // Phase C+D fused in registers: h2 = tanh(acc2+b2); p[h] = h2 . W3; quad reduce; RMW P
    float p0[8], p1[8];
#pragma unroll
    for (int h = 0; h < 8; h++) { p0[h] = 0.f; p1[h] = 0.f; }

#pragma unroll
    for (int nt = 0; nt < 8; nt++) {
        int col0 = nt * 8 + 2 * t, col1 = col0 + 1;
        float b0 = sb2[col0], b1v = sb2[col1];
        float h00 = ftanh(acc2[nt][0] + b0);
        float h01 = ftanh(acc2[nt][1] + b1v);
        float h10 = ftanh(acc2[nt][2] + b0);
        float h11 = ftanh(acc2[nt][3] + b1v);
        float4 wa0 = *(float4*)&sW3[col0 * 8];
        float4 wa1 = *(float4*)&sW3[col0 * 8 + 4];
        float4 wb0 = *(float4*)&sW3[col1 * 8];
        float4 wb1 = *(float4*)&sW3[col1 * 8 + 4];
        p0[0] += h00 * wa0.x + h01 * wb0.x;  p0[1] += h00 * wa0.y + h01 * wb0.y;
        p0[2] += h00 * wa0.z + h01 * wb0.z;  p0[3] += h00 * wa0.w + h01 * wb0.w;
        p0[4] += h00 * wa1.x + h01 * wb1.x;  p0[5] += h00 * wa1.y + h01 * wb1.y;
        p0[6] += h00 * wa1.z + h01 * wb1.z;  p0[7] += h00 * wa1.w + h01 * wb1.w;
        p1[0] += h10 * wa0.x + h11 * wb0.x;  p1[1] += h10 * wa0.y + h11 * wb0.y;
        p1[2] += h10 * wa0.z + h11 * wb0.z;  p1[3] += h10 * wa0.w + h11 * wb0.w;
        p1[4] += h10 * wa1.x + h11 * wb1.x;  p1[5] += h10 * wa1.y + h11 * wb1.y;
        p1[6] += h10 * wa1.z + h11 * wb1.z;  p1[7] += h10 * wa1.w + h11 * wb1.w;
    }
#pragma unroll
    for (int h = 0; h < 8; h++) {
        p0[h] += __shfl_xor_sync(0xffffffffu, p0[h], 1);
        p0[h] += __shfl_xor_sync(0xffffffffu, p0[h], 2);
        p1[h] += __shfl_xor_sync(0xffffffffu, p1[h], 1);
        p1[h] += __shfl_xor_sync(0xffffffffu, p1[h], 2);
    }
    int sg0 = s0 + row0, sg1 = sg0 + 8;
#pragma unroll
    for (int hh2 = 0; hh2 < 2; hh2++) {
        int h = 2 * t + hh2;
        float* P0 = &g_P[(size_t)h * (N_NODES * N_NODES) + (size_t)r * 512 + sg0];
        float* P1 = &g_P[(size_t)h * (N_NODES * N_NODES) + (size_t)r * 512 + sg1];
        *P0 += p0[h] + sb3[h];
        *P1 += p1[h] + sb3[h];
    }
}

// ================= Kernel 5: softmax + aggregation + residual =================
#define SW_STRIDE 520
#define SMEM3_BYTES (4 * 8 * SW_STRIDE * 4)

__device__ __forceinline__ int h_of(int c) {
    if (c < 128) return c >> 4;
    if (c < 320) return ((c - 128) / 3) >> 3;
    return ((c - 320) / 5) >> 2;
}

__global__ void __launch_bounds__(256) k_out(
    const float* __restrict__ node_feat, float* __restrict__ out)
{
    extern __shared__ float sw[];  // [4][8][520]
    int tid = threadIdx.x;
    int r0 = blockIdx.x * 4;

    for (int i = tid; i < 4096; i += 256) {
        int rr = i >> 10, rem = i & 1023;
        int hh = rem >> 7, s4 = rem & 127;
        float4 v = *(const float4*)&g_P[(size_t)hh * (N_NODES * N_NODES) +
                                        (size_t)(r0 + rr) * N_NODES + s4 * 4];
        float* dst = &sw[(rr * 8 + hh) * SW_STRIDE + s4 * 4];
        dst[0] = v.x; dst[1] = v.y; dst[2] = v.z; dst[3] = v.w;
    }
    __syncthreads();

    int wid = tid >> 5, lane = tid & 31;
    for (int p = wid; p < 32; p += 8) {
        float* row = &sw[p * SW_STRIDE];
        float mx = -1e30f;
#pragma unroll
        for (int k = 0; k < 16; k++) mx = fmaxf(mx, row[lane + 32 * k]);
#pragma unroll
        for (int off = 16; off; off >>= 1) mx = fmaxf(mx, __shfl_xor_sync(0xffffffffu, mx, off));
        float sum = 0.f;
#pragma unroll
        for (int k = 0; k < 16; k++) sum += __expf(row[lane + 32 * k] - mx);
#pragma unroll
        for (int off = 16; off; off >>= 1) sum += __shfl_xor_sync(0xffffffffu, sum, off);
        float rinv = __fdividef(1.0f, sum);
#pragma unroll
        for (int k = 0; k < 16; k++) {
            int s = lane + 32 * k;
            row[s] = __expf(row[s] - mx) * rinv;
        }
    }
    __syncthreads();

    for (int c = wid; c < 480; c += 8) {
        int hh = h_of(c);
        const float* vrow = &g_vmT[(size_t)c * N_NODES];
        const float* w0 = &sw[(0 * 8 + hh) * SW_STRIDE];
        const float* w1 = &sw[(1 * 8 + hh) * SW_STRIDE];
        const float* w2 = &sw[(2 * 8 + hh) * SW_STRIDE];
        const float* w3 = &sw[(3 * 8 + hh) * SW_STRIDE];
        float a0 = 0.f, a1 = 0.f, a2 = 0.f, a3 = 0.f;
#pragma unroll
        for (int k = 0; k < 16; k++) {
            int s = k * 32 + lane;
            float vv = vrow[s];
            a0 += w0[s] * vv; a1 += w1[s] * vv; a2 += w2[s] * vv; a3 += w3[s] * vv;
        }
#pragma unroll
        for (int off = 16; off; off >>= 1) {
            a0 += __shfl_xor_sync(0xffffffffu, a0, off);
            a1 += __shfl_xor_sync(0xffffffffu, a1, off);
            a2 += __shfl_xor_sync(0xffffffffu, a2, off);
            a3 += __shfl_xor_sync(0xffffffffu, a3, off);
        }
        if (lane == 0) {
            out[(size_t)(r0 + 0) * 480 + c] = node_feat[(size_t)(r0 + 0) * 480 + c] + a0;
            out[(size_t)(r0 + 1) * 480 + c] = node_feat[(size_t)(r0 + 1) * 480 + c] + a1;
            out[(size_t)(r0 + 2) * 480 + c] = node_feat[(size_t)(r0 + 2) * 480 + c] + a2;
            out[(size_t)(r0 + 3) * 480 + c] = node_feat[(size_t)(r0 + 3) * 480 + c] + a3;
        }
    }
}

// ================= launch =================
extern "C" void kernel_launch(void* const* d_in, const int* in_sizes, int n_in,
                              void* d_out, int out_size)
{
    const float* node_feat = (const float*)d_in[0];
    const float* edge_attr = (const float*)d_in[1];
    const float* edge_sh   = (const float*)d_in[2];
    const float* Wq0 = (const float*)d_in[3];
    const float* Wq1 = (const float*)d_in[4];
    const float* Wq2 = (const float*)d_in[5];
    const float* Wk0 = (const float*)d_in[6];
    const float* Wk1 = (const float*)d_in[7];
    const float* Wk2 = (const float*)d_in[8];
    const float* Wv0 = (const float*)d_in[9];
    const float* Wv1 = (const float*)d_in[10];
    const float* Wv2 = (const float*)d_in[11];
    const float* mW1 = (const float*)d_in[12];
    const float* mb1 = (const float*)d_in[13];
    const float* mW2 = (const float*)d_in[14];
    const float* mb2 = (const float*)d_in[15];
    const float* mW3 = (const float*)d_in[16];
    const float* mb3 = (const float*)d_in[17];
    float* out = (float*)d_out;

    cudaFuncSetAttribute(k_mlp, cudaFuncAttributeMaxDynamicSharedMemorySize, SMEM_MLP);
    cudaFuncSetAttribute(k_out, cudaFuncAttributeMaxDynamicSharedMemorySize, SMEM3_BYTES);

    k_node<<<dim3(128, 2), 256>>>(node_feat, Wq0, Wq1, Wq2, Wk0, Wk1, Wk2, Wv0, Wv1, Wv2, mW1);
    k_X<<<2048, 256>>>(edge_attr, edge_sh, mW1, mb1);
    k_logit<<<512, 256>>>();
    k_mlp<<<2048, 256, SMEM_MLP>>>(edge_sh, mW2, mb2, mW3, mb3);
    k_out<<<128, 256, SMEM3_BYTES>>>(node_feat, out);
}